// round 1
// baseline (speedup 1.0000x reference)
#include <cuda_runtime.h>
#include <math.h>

#define S_LEN 4096
#define DMODEL 768
#define NHEADS 12
#define DHEAD 64

// Scratch (static device globals — no allocation allowed)
__device__ float g_Qh[NHEADS * S_LEN * DHEAD];   // [h][s][d]
__device__ float g_Kh[NHEADS * S_LEN * DHEAD];
__device__ float g_Vh[NHEADS * S_LEN * DHEAD];
__device__ float g_Ctx[S_LEN * DMODEL];          // [s][dmodel]

// ---------------------------------------------------------------------------
// Projection GEMM: C[m,n] = sum_k A[m,k] * W[n,k] + bias[n]
// M=4096, N=768, K=768. BM=BN=128, BK=8, 256 threads, 8x8 per-thread tile.
// MODE 0/1/2: scatter head-major into g_Qh/g_Kh/g_Vh. MODE 3: A := g_Ctx,
// write row-major to Out.
// ---------------------------------------------------------------------------
template<int MODE>
__global__ __launch_bounds__(256)
void proj_gemm(const float* __restrict__ A_in, const float* __restrict__ W,
               const float* __restrict__ bias, float* __restrict__ Out)
{
    const float* A = (MODE == 3) ? g_Ctx : A_in;

    __shared__ float As[8][132];
    __shared__ float Bs[8][132];

    const int tid = threadIdx.x;
    const int m0 = blockIdx.y * 128;
    const int n0 = blockIdx.x * 128;

    const int lm = tid >> 1;          // 0..127  (row within tile)
    const int lk = (tid & 1) * 4;     // 0 or 4  (k offset, float4)

    const int tx = tid & 15;          // col group
    const int ty = tid >> 4;          // row group

    float acc[8][8];
#pragma unroll
    for (int i = 0; i < 8; i++)
#pragma unroll
        for (int j = 0; j < 8; j++) acc[i][j] = 0.f;

    for (int k0 = 0; k0 < DMODEL; k0 += 8) {
        float4 a = *(const float4*)(A + (size_t)(m0 + lm) * DMODEL + k0 + lk);
        float4 b = *(const float4*)(W + (size_t)(n0 + lm) * DMODEL + k0 + lk);
        __syncthreads();   // previous compute done before overwrite
        As[lk + 0][lm] = a.x; As[lk + 1][lm] = a.y;
        As[lk + 2][lm] = a.z; As[lk + 3][lm] = a.w;
        Bs[lk + 0][lm] = b.x; Bs[lk + 1][lm] = b.y;
        Bs[lk + 2][lm] = b.z; Bs[lk + 3][lm] = b.w;
        __syncthreads();

#pragma unroll
        for (int kk = 0; kk < 8; kk++) {
            float ar[8], br[8];
            *(float4*)(ar)     = *(float4*)&As[kk][ty * 8];
            *(float4*)(ar + 4) = *(float4*)&As[kk][ty * 8 + 4];
            *(float4*)(br)     = *(float4*)&Bs[kk][tx * 8];
            *(float4*)(br + 4) = *(float4*)&Bs[kk][tx * 8 + 4];
#pragma unroll
            for (int i = 0; i < 8; i++)
#pragma unroll
                for (int j = 0; j < 8; j++)
                    acc[i][j] = fmaf(ar[i], br[j], acc[i][j]);
        }
    }

    // Epilogue
#pragma unroll
    for (int i = 0; i < 8; i++) {
        int m = m0 + ty * 8 + i;
#pragma unroll
        for (int jg = 0; jg < 8; jg += 4) {
            int n = n0 + tx * 8 + jg;
            float4 bz = *(const float4*)(bias + n);
            float4 o;
            o.x = acc[i][jg + 0] + bz.x;
            o.y = acc[i][jg + 1] + bz.y;
            o.z = acc[i][jg + 2] + bz.z;
            o.w = acc[i][jg + 3] + bz.w;
            if (MODE == 3) {
                *(float4*)(Out + (size_t)m * DMODEL + n) = o;
            } else {
                int h = n >> 6;
                int d = n & 63;
                float* base = (MODE == 0) ? g_Qh : (MODE == 1) ? g_Kh : g_Vh;
                *(float4*)(base + ((size_t)h * S_LEN + m) * DHEAD + d) = o;
            }
        }
    }
}

// ---------------------------------------------------------------------------
// Flash attention (causal). Grid: (64 q-blocks, 12 heads), 256 threads.
// BM=BN=64, d=64. Q/K smem d-major for conflict-free float4 outer products.
// ---------------------------------------------------------------------------
#define ATTN_SMEM_FLOATS (64*64*3 + 64*65)
#define ATTN_SMEM_BYTES  (ATTN_SMEM_FLOATS * 4)

__global__ __launch_bounds__(256)
void flash_attn()
{
    extern __shared__ float sm[];
    float* Qs = sm;                 // [d][r]  (64 x 64)
    float* Ks = sm + 4096;          // [d][c]  (64 x 64)
    float* Vs = sm + 8192;          // [n][d]  (64 x 64)
    float* Ps = sm + 12288;         // [n][r]  (64 x 65, padded)

    const int tid  = threadIdx.x;
    const int head = blockIdx.y;
    const int q0   = blockIdx.x * 64;

    const float* Qg = g_Qh + (size_t)head * S_LEN * DHEAD;
    const float* Kg = g_Kh + (size_t)head * S_LEN * DHEAD;
    const float* Vg = g_Vh + (size_t)head * S_LEN * DHEAD;

    const int tx = tid & 15;        // col group (keys / dims)
    const int ty = tid >> 4;        // row group (queries)
    const int r0 = ty * 4;
    const int c0 = tx * 4;

    // Load Q tile transposed into Qs[d][r]
#pragma unroll
    for (int i = 0; i < 4; i++) {
        int idx = tid + i * 256;          // 0..1023
        int r   = idx >> 4;
        int dq  = (idx & 15) * 4;
        float4 v4 = *(const float4*)(Qg + (size_t)(q0 + r) * DHEAD + dq);
        Qs[(dq + 0) * 64 + r] = v4.x;
        Qs[(dq + 1) * 64 + r] = v4.y;
        Qs[(dq + 2) * 64 + r] = v4.z;
        Qs[(dq + 3) * 64 + r] = v4.w;
    }

    float m_i[4], l_i[4], acc[4][4];
#pragma unroll
    for (int i = 0; i < 4; i++) {
        m_i[i] = -1e30f;
        l_i[i] = 0.f;
#pragma unroll
        for (int j = 0; j < 4; j++) acc[i][j] = 0.f;
    }

    const float scale = 0.125f;     // 1/sqrt(64)
    const int ntiles = (q0 >> 6) + 1;

    for (int t = 0; t < ntiles; t++) {
        const int kv0 = t * 64;
        __syncthreads();            // previous PV done before overwrite
        // Load K (transposed) and V (natural)
#pragma unroll
        for (int i = 0; i < 4; i++) {
            int idx = tid + i * 256;
            int r   = idx >> 4;
            int dq  = (idx & 15) * 4;
            float4 kv = *(const float4*)(Kg + (size_t)(kv0 + r) * DHEAD + dq);
            Ks[(dq + 0) * 64 + r] = kv.x;
            Ks[(dq + 1) * 64 + r] = kv.y;
            Ks[(dq + 2) * 64 + r] = kv.z;
            Ks[(dq + 3) * 64 + r] = kv.w;
            float4 vv = *(const float4*)(Vg + (size_t)(kv0 + r) * DHEAD + dq);
            *(float4*)(Vs + r * 64 + dq) = vv;
        }
        __syncthreads();

        // S = Q K^T (4x4 per thread)
        float s[4][4];
#pragma unroll
        for (int i = 0; i < 4; i++)
#pragma unroll
            for (int j = 0; j < 4; j++) s[i][j] = 0.f;

#pragma unroll 8
        for (int d = 0; d < 64; d++) {
            float4 rq = *(float4*)(Qs + d * 64 + r0);
            float4 rk = *(float4*)(Ks + d * 64 + c0);
            float qv[4] = {rq.x, rq.y, rq.z, rq.w};
            float kvv[4] = {rk.x, rk.y, rk.z, rk.w};
#pragma unroll
            for (int i = 0; i < 4; i++)
#pragma unroll
                for (int j = 0; j < 4; j++)
                    s[i][j] = fmaf(qv[i], kvv[j], s[i][j]);
        }

        const bool diag = (kv0 == q0);
#pragma unroll
        for (int i = 0; i < 4; i++) {
            int qi = q0 + r0 + i;
#pragma unroll
            for (int j = 0; j < 4; j++) {
                s[i][j] *= scale;
                if (diag && (kv0 + c0 + j) > qi) s[i][j] = -1e30f;
            }
        }

        // Online softmax per row + write P to smem
#pragma unroll
        for (int i = 0; i < 4; i++) {
            float tmax = fmaxf(fmaxf(s[i][0], s[i][1]), fmaxf(s[i][2], s[i][3]));
#pragma unroll
            for (int msk = 1; msk < 16; msk <<= 1)
                tmax = fmaxf(tmax, __shfl_xor_sync(0xffffffffu, tmax, msk, 16));
            float mnew = fmaxf(m_i[i], tmax);
            float esc  = __expf(m_i[i] - mnew);
            float psum = 0.f;
#pragma unroll
            for (int j = 0; j < 4; j++) {
                float p = __expf(s[i][j] - mnew);
                s[i][j] = p;
                psum += p;
            }
#pragma unroll
            for (int msk = 1; msk < 16; msk <<= 1)
                psum += __shfl_xor_sync(0xffffffffu, psum, msk, 16);
            l_i[i] = l_i[i] * esc + psum;
            m_i[i] = mnew;
#pragma unroll
            for (int j = 0; j < 4; j++) {
                acc[i][j] *= esc;
                Ps[(c0 + j) * 65 + (r0 + i)] = s[i][j];
            }
        }
        __syncthreads();

        // O += P V   (dims owned: d = c0..c0+3)
#pragma unroll 8
        for (int n = 0; n < 64; n++) {
            float4 rv = *(float4*)(Vs + n * 64 + c0);
            float vv[4] = {rv.x, rv.y, rv.z, rv.w};
#pragma unroll
            for (int i = 0; i < 4; i++) {
                float rp = Ps[n * 65 + r0 + i];
#pragma unroll
                for (int j = 0; j < 4; j++)
                    acc[i][j] = fmaf(rp, vv[j], acc[i][j]);
            }
        }
    }

    // Epilogue: normalize and write context row-major [s][dmodel]
#pragma unroll
    for (int i = 0; i < 4; i++) {
        float inv = 1.f / l_i[i];
        float4 o;
        o.x = acc[i][0] * inv;
        o.y = acc[i][1] * inv;
        o.z = acc[i][2] * inv;
        o.w = acc[i][3] * inv;
        *(float4*)(g_Ctx + (size_t)(q0 + r0 + i) * DMODEL + head * DHEAD + c0) = o;
    }
}

// ---------------------------------------------------------------------------
extern "C" void kernel_launch(void* const* d_in, const int* in_sizes, int n_in,
                              void* d_out, int out_size)
{
    const float* q  = (const float*)d_in[0];
    const float* k  = (const float*)d_in[1];
    const float* v  = (const float*)d_in[2];
    const float* wq = (const float*)d_in[3];
    const float* bq = (const float*)d_in[4];
    const float* wk = (const float*)d_in[5];
    const float* bk = (const float*)d_in[6];
    const float* wv = (const float*)d_in[7];
    const float* bv = (const float*)d_in[8];
    const float* wo = (const float*)d_in[9];
    const float* bo = (const float*)d_in[10];
    float* out = (float*)d_out;

    dim3 gg(DMODEL / 128, S_LEN / 128);   // (6, 32)

    proj_gemm<0><<<gg, 256>>>(q, wq, bq, nullptr);
    proj_gemm<1><<<gg, 256>>>(k, wk, bk, nullptr);
    proj_gemm<2><<<gg, 256>>>(v, wv, bv, nullptr);

    cudaFuncSetAttribute(flash_attn, cudaFuncAttributeMaxDynamicSharedMemorySize,
                         ATTN_SMEM_BYTES);
    flash_attn<<<dim3(S_LEN / 64, NHEADS), 256, ATTN_SMEM_BYTES>>>();

    proj_gemm<3><<<gg, 256>>>(nullptr, wo, bo, out);
}

// round 3
// speedup vs baseline: 1.3836x; 1.3836x over previous
#include <cuda_runtime.h>
#include <cstdint>
#include <math.h>

#define S_LEN 4096
#define DMODEL 768
#define NHEADS 12
#define DHEAD 64

// Scratch (static device globals — no allocation allowed)
__device__ float g_Qh[NHEADS * S_LEN * DHEAD];   // [h][s][d]
__device__ float g_Kh[NHEADS * S_LEN * DHEAD];
__device__ float g_Vh[NHEADS * S_LEN * DHEAD];
__device__ float g_Ctx[S_LEN * DMODEL];          // [s][dmodel]

// ---------------------------------------------------------------------------
// PTX helpers (sm_80-era PTX only — compute_103 baseline-safe, no tcgen05)
// ---------------------------------------------------------------------------
__device__ __forceinline__ uint32_t smem_u32(const void* p) {
    uint32_t a;
    asm("{ .reg .u64 t; cvta.to.shared.u64 t, %1; cvt.u32.u64 %0, t; }"
        : "=r"(a) : "l"(p));
    return a;
}

#define CP_ASYNC16(dst, src) \
    asm volatile("cp.async.cg.shared.global [%0], [%1], 16;" \
                 :: "r"(dst), "l"(src))
#define CP_COMMIT() asm volatile("cp.async.commit_group;" ::: "memory")
#define CP_WAIT3()  asm volatile("cp.async.wait_group 3;" ::: "memory")

__device__ __forceinline__ void ldsm_x4(uint32_t* r, uint32_t addr) {
    asm volatile("ldmatrix.sync.aligned.m8n8.x4.shared.b16 {%0,%1,%2,%3}, [%4];"
                 : "=r"(r[0]), "=r"(r[1]), "=r"(r[2]), "=r"(r[3]) : "r"(addr));
}
__device__ __forceinline__ void ldsm_x2(uint32_t* r, uint32_t addr) {
    asm volatile("ldmatrix.sync.aligned.m8n8.x2.shared.b16 {%0,%1}, [%2];"
                 : "=r"(r[0]), "=r"(r[1]) : "r"(addr));
}
__device__ __forceinline__ uint32_t f2tf32(uint32_t x) {
    uint32_t o;
    asm("cvt.rna.tf32.f32 %0, %1;" : "=r"(o) : "f"(__uint_as_float(x)));
    return o;
}
__device__ __forceinline__ void mma_tf32(float* c, const uint32_t* a, const uint32_t* b) {
    asm volatile(
        "mma.sync.aligned.m16n8k8.row.col.f32.tf32.tf32.f32 "
        "{%0,%1,%2,%3}, {%4,%5,%6,%7}, {%8,%9}, {%0,%1,%2,%3};"
        : "+f"(c[0]), "+f"(c[1]), "+f"(c[2]), "+f"(c[3])
        : "r"(a[0]), "r"(a[1]), "r"(a[2]), "r"(a[3]), "r"(b[0]), "r"(b[1]));
}

// ---------------------------------------------------------------------------
// TF32 tensor-core GEMM: C[m,n] = sum_k A[m,k] * W[n,k] + bias[n]
// M=4096, N=768, K=768. Tile 128x128, BK=16, 256 threads (8 warps, 2m x 4n,
// each warp 64x32). 4-stage cp.async pipeline. Smem rows padded to 20 words
// (80B) -> LDSM 8-row pattern is bank-conflict-free without swizzle.
// MODE 0/1/2: scatter head-major into g_Qh/g_Kh/g_Vh. MODE 3: A := g_Ctx.
// ---------------------------------------------------------------------------
#define ROWW 20                             // padded row length in words
#define HALF_STAGE_BYTES (128 * ROWW * 4)   // 10240 (A or B tile)
#define STAGE_BYTES (2 * HALF_STAGE_BYTES)  // 20480
#define NSTAGE 4
#define GEMM_SMEM_BYTES (NSTAGE * STAGE_BYTES)  // 81920
#define KT_TILES 48                         // 768 / 16

template<int MODE>
__global__ __launch_bounds__(256)
void gemm_mma(const float* __restrict__ A_in, const float* __restrict__ W,
              const float* __restrict__ bias, float* __restrict__ Out)
{
    extern __shared__ float sm[];
    const uint32_t sbase = smem_u32(sm);

    const int tid  = threadIdx.x;
    const int lane = tid & 31;
    const int wid  = tid >> 5;
    const int m0 = blockIdx.y * 128;
    const int n0 = blockIdx.x * 128;
    const int warp_m = (wid & 1) * 64;
    const int warp_n = (wid >> 1) * 32;

    const float* Ag = (MODE == 3) ? (const float*)g_Ctx : A_in;
    const char* gA = (const char*)(Ag + (size_t)m0 * DMODEL);
    const char* gB = (const char*)(W + (size_t)n0 * DMODEL);

    // Copy decomposition: 1024 16B chunks/stage (512 A + 512 B), 4 per thread.
    auto issue = [&](int kt) {
        int stage = kt & (NSTAGE - 1);
        uint32_t dstBase = sbase + stage * STAGE_BYTES;
#pragma unroll
        for (int c = 0; c < 4; c++) {
            int idx = tid + c * 256;        // 0..1023
            int mat = idx >> 9;             // 0: A, 1: B
            int i   = idx & 511;
            int row = i >> 2;               // 0..127
            int ch  = i & 3;                // 16B chunk in row
            uint32_t dst = dstBase + mat * HALF_STAGE_BYTES + row * (ROWW * 4) + ch * 16;
            const char* src = (mat ? gB : gA) + (size_t)row * 3072 + (size_t)kt * 64 + ch * 16;
            CP_ASYNC16(dst, src);
        }
    };

    float acc[4][4][4];
#pragma unroll
    for (int i = 0; i < 4; i++)
#pragma unroll
        for (int j = 0; j < 4; j++)
#pragma unroll
            for (int r = 0; r < 4; r++) acc[i][j][r] = 0.f;

    issue(0); CP_COMMIT();
    issue(1); CP_COMMIT();
    issue(2); CP_COMMIT();

    // Precomputed lane decompositions for LDSM addressing
    const int a_rowoff = ((lane >> 3) & 1) * 8 + (lane & 7);  // row within 16-row atom
    const int a_half   = (lane >> 4) & 1;                     // k half (0: k0-3, 1: k4-7)
    const int b_l      = lane & 15;
    const int b_row    = b_l & 7;
    const int b_half   = (b_l >> 3) & 1;

    for (int kt = 0; kt < KT_TILES; kt++) {
        if (kt + 3 < KT_TILES) issue(kt + 3);
        CP_COMMIT();                 // empty groups at tail keep wait-count uniform
        CP_WAIT3();
        __syncthreads();

        uint32_t aS = sbase + (kt & (NSTAGE - 1)) * STAGE_BYTES;
        uint32_t bS = aS + HALF_STAGE_BYTES;

#pragma unroll
        for (int ks = 0; ks < 2; ks++) {          // two k8 steps per BK=16 tile
            uint32_t a[4][4], b[4][2];
#pragma unroll
            for (int am = 0; am < 4; am++) {
                uint32_t addr = aS + (warp_m + am * 16 + a_rowoff) * (ROWW * 4)
                              + ks * 32 + a_half * 16;
                ldsm_x4(a[am], addr);
            }
#pragma unroll
            for (int bn = 0; bn < 4; bn++) {
                uint32_t addr = bS + (warp_n + bn * 8 + b_row) * (ROWW * 4)
                              + ks * 32 + b_half * 16;
                ldsm_x2(b[bn], addr);
            }
#pragma unroll
            for (int am = 0; am < 4; am++)
#pragma unroll
                for (int j = 0; j < 4; j++) a[am][j] = f2tf32(a[am][j]);
#pragma unroll
            for (int bn = 0; bn < 4; bn++) {
                b[bn][0] = f2tf32(b[bn][0]);
                b[bn][1] = f2tf32(b[bn][1]);
            }
#pragma unroll
            for (int am = 0; am < 4; am++)
#pragma unroll
                for (int bn = 0; bn < 4; bn++)
                    mma_tf32(acc[am][bn], a[am], b[bn]);
        }
        __syncthreads();
    }

    // Epilogue: fragment c -> (row g/g+8, cols 2*tig, 2*tig+1)
    const int g   = lane >> 2;
    const int tig = lane & 3;
#pragma unroll
    for (int am = 0; am < 4; am++) {
#pragma unroll
        for (int bn = 0; bn < 4; bn++) {
            int ncol = n0 + warp_n + bn * 8 + tig * 2;
            float2 bz = *(const float2*)(bias + ncol);
#pragma unroll
            for (int h = 0; h < 2; h++) {
                int m = m0 + warp_m + am * 16 + g + h * 8;
                float2 o;
                o.x = acc[am][bn][h * 2 + 0] + bz.x;
                o.y = acc[am][bn][h * 2 + 1] + bz.y;
                if (MODE == 3) {
                    *(float2*)(Out + (size_t)m * DMODEL + ncol) = o;
                } else {
                    int hd = ncol >> 6;
                    int d  = ncol & 63;
                    float* base = (MODE == 0) ? g_Qh : (MODE == 1) ? g_Kh : g_Vh;
                    *(float2*)(base + ((size_t)hd * S_LEN + m) * DHEAD + d) = o;
                }
            }
        }
    }
}

// ---------------------------------------------------------------------------
// Flash attention (causal, fp32). BM=128 q-rows, BN=64 keys, 256 threads.
// Thread grid 16x16: ty owns 8 q-rows, tx owns 4 key-cols / 4 out-dims.
// ---------------------------------------------------------------------------
#define ATTN_SMEM_FLOATS (64*128 + 64*64 + 64*64 + 64*132)
#define ATTN_SMEM_BYTES  (ATTN_SMEM_FLOATS * 4)

__global__ __launch_bounds__(256, 2)
void flash_attn()
{
    extern __shared__ float sm[];
    float* Qs = sm;                  // [d][r]  64 x 128
    float* Ks = sm + 8192;           // [d][c]  64 x 64
    float* Vs = sm + 12288;          // [n][d]  64 x 64
    float* Ps = sm + 16384;          // [n][r]  64 x 132 (padded)

    const int tid  = threadIdx.x;
    const int head = blockIdx.y;
    const int qb   = gridDim.x - 1 - blockIdx.x;   // largest workload first
    const int q0   = qb * 128;

    const float* Qg = g_Qh + (size_t)head * S_LEN * DHEAD;
    const float* Kg = g_Kh + (size_t)head * S_LEN * DHEAD;
    const float* Vg = g_Vh + (size_t)head * S_LEN * DHEAD;

    const int tx = tid & 15;
    const int ty = tid >> 4;
    const int r0 = ty * 8;
    const int c0 = tx * 4;

    // Load Q tile transposed into Qs[d][r] : 128 rows x 64 d
#pragma unroll
    for (int i = 0; i < 8; i++) {
        int idx = tid + i * 256;          // 0..2047
        int r   = idx >> 4;               // 0..127
        int dq  = (idx & 15) * 4;
        float4 v4 = *(const float4*)(Qg + (size_t)(q0 + r) * DHEAD + dq);
        Qs[(dq + 0) * 128 + r] = v4.x;
        Qs[(dq + 1) * 128 + r] = v4.y;
        Qs[(dq + 2) * 128 + r] = v4.z;
        Qs[(dq + 3) * 128 + r] = v4.w;
    }

    float m_i[8], l_i[8], acc[8][4];
#pragma unroll
    for (int i = 0; i < 8; i++) {
        m_i[i] = -1e30f;
        l_i[i] = 0.f;
#pragma unroll
        for (int j = 0; j < 4; j++) acc[i][j] = 0.f;
    }

    const float scale = 0.125f;     // 1/sqrt(64)
    const int ntiles = 2 * qb + 2;

    for (int t = 0; t < ntiles; t++) {
        const int kv0 = t * 64;
        __syncthreads();            // previous PV done before overwrite
#pragma unroll
        for (int i = 0; i < 4; i++) {
            int idx = tid + i * 256;     // 0..1023
            int r   = idx >> 4;          // 0..63
            int dq  = (idx & 15) * 4;
            float4 kv = *(const float4*)(Kg + (size_t)(kv0 + r) * DHEAD + dq);
            Ks[(dq + 0) * 64 + r] = kv.x;
            Ks[(dq + 1) * 64 + r] = kv.y;
            Ks[(dq + 2) * 64 + r] = kv.z;
            Ks[(dq + 3) * 64 + r] = kv.w;
            float4 vv = *(const float4*)(Vg + (size_t)(kv0 + r) * DHEAD + dq);
            *(float4*)(Vs + r * 64 + dq) = vv;
        }
        __syncthreads();

        // S = Q K^T  (8x4 per thread)
        float s[8][4];
#pragma unroll
        for (int i = 0; i < 8; i++)
#pragma unroll
            for (int j = 0; j < 4; j++) s[i][j] = 0.f;

#pragma unroll 4
        for (int d = 0; d < 64; d++) {
            float4 a0 = *(float4*)(Qs + d * 128 + r0);
            float4 a1 = *(float4*)(Qs + d * 128 + r0 + 4);
            float4 b  = *(float4*)(Ks + d * 64 + c0);
            float av[8] = {a0.x, a0.y, a0.z, a0.w, a1.x, a1.y, a1.z, a1.w};
            float bv[4] = {b.x, b.y, b.z, b.w};
#pragma unroll
            for (int i = 0; i < 8; i++)
#pragma unroll
                for (int j = 0; j < 4; j++)
                    s[i][j] = fmaf(av[i], bv[j], s[i][j]);
        }

        const bool need_mask = (t >= 2 * qb);
#pragma unroll
        for (int i = 0; i < 8; i++) {
            int qi = q0 + r0 + i;
#pragma unroll
            for (int j = 0; j < 4; j++) {
                s[i][j] *= scale;
                if (need_mask && (kv0 + c0 + j) > qi) s[i][j] = -1e30f;
            }
        }

        // Online softmax per row + write P (transposed) to smem
#pragma unroll
        for (int i = 0; i < 8; i++) {
            float tmax = fmaxf(fmaxf(s[i][0], s[i][1]), fmaxf(s[i][2], s[i][3]));
#pragma unroll
            for (int msk = 1; msk < 16; msk <<= 1)
                tmax = fmaxf(tmax, __shfl_xor_sync(0xffffffffu, tmax, msk, 16));
            float mnew = fmaxf(m_i[i], tmax);
            float esc  = __expf(m_i[i] - mnew);
            float psum = 0.f;
#pragma unroll
            for (int j = 0; j < 4; j++) {
                float p = __expf(s[i][j] - mnew);
                s[i][j] = p;
                psum += p;
            }
#pragma unroll
            for (int msk = 1; msk < 16; msk <<= 1)
                psum += __shfl_xor_sync(0xffffffffu, psum, msk, 16);
            l_i[i] = l_i[i] * esc + psum;
            m_i[i] = mnew;
#pragma unroll
            for (int j = 0; j < 4; j++) {
                acc[i][j] *= esc;
                Ps[(c0 + j) * 132 + (r0 + i)] = s[i][j];
            }
        }
        __syncthreads();

        // O += P V   (out dims owned: c0..c0+3)
#pragma unroll 4
        for (int n = 0; n < 64; n++) {
            float4 v  = *(float4*)(Vs + n * 64 + c0);
            float4 p0 = *(float4*)(Ps + n * 132 + r0);
            float4 p1 = *(float4*)(Ps + n * 132 + r0 + 4);
            float vv[4] = {v.x, v.y, v.z, v.w};
            float pv[8] = {p0.x, p0.y, p0.z, p0.w, p1.x, p1.y, p1.z, p1.w};
#pragma unroll
            for (int i = 0; i < 8; i++)
#pragma unroll
                for (int j = 0; j < 4; j++)
                    acc[i][j] = fmaf(pv[i], vv[j], acc[i][j]);
        }
    }

    // Epilogue: normalize and write context row-major [s][dmodel]
#pragma unroll
    for (int i = 0; i < 8; i++) {
        float inv = 1.f / l_i[i];
        float4 o;
        o.x = acc[i][0] * inv;
        o.y = acc[i][1] * inv;
        o.z = acc[i][2] * inv;
        o.w = acc[i][3] * inv;
        *(float4*)(g_Ctx + (size_t)(q0 + r0 + i) * DMODEL + head * DHEAD + c0) = o;
    }
}

// ---------------------------------------------------------------------------
extern "C" void kernel_launch(void* const* d_in, const int* in_sizes, int n_in,
                              void* d_out, int out_size)
{
    const float* q  = (const float*)d_in[0];
    const float* k  = (const float*)d_in[1];
    const float* v  = (const float*)d_in[2];
    const float* wq = (const float*)d_in[3];
    const float* bq = (const float*)d_in[4];
    const float* wk = (const float*)d_in[5];
    const float* bk = (const float*)d_in[6];
    const float* wv = (const float*)d_in[7];
    const float* bv = (const float*)d_in[8];
    const float* wo = (const float*)d_in[9];
    const float* bo = (const float*)d_in[10];
    float* out = (float*)d_out;

    cudaFuncSetAttribute(gemm_mma<0>, cudaFuncAttributeMaxDynamicSharedMemorySize, GEMM_SMEM_BYTES);
    cudaFuncSetAttribute(gemm_mma<1>, cudaFuncAttributeMaxDynamicSharedMemorySize, GEMM_SMEM_BYTES);
    cudaFuncSetAttribute(gemm_mma<2>, cudaFuncAttributeMaxDynamicSharedMemorySize, GEMM_SMEM_BYTES);
    cudaFuncSetAttribute(gemm_mma<3>, cudaFuncAttributeMaxDynamicSharedMemorySize, GEMM_SMEM_BYTES);
    cudaFuncSetAttribute(flash_attn, cudaFuncAttributeMaxDynamicSharedMemorySize, ATTN_SMEM_BYTES);

    dim3 gg(DMODEL / 128, S_LEN / 128);   // (6, 32)

    gemm_mma<0><<<gg, 256, GEMM_SMEM_BYTES>>>(q, wq, bq, nullptr);
    gemm_mma<1><<<gg, 256, GEMM_SMEM_BYTES>>>(k, wk, bk, nullptr);
    gemm_mma<2><<<gg, 256, GEMM_SMEM_BYTES>>>(v, wv, bv, nullptr);

    flash_attn<<<dim3(S_LEN / 128, NHEADS), 256, ATTN_SMEM_BYTES>>>();

    gemm_mma<3><<<gg, 256, GEMM_SMEM_BYTES>>>(nullptr, wo, bo, out);
}

// round 4
// speedup vs baseline: 2.6990x; 1.9508x over previous
#include <cuda_runtime.h>
#include <cstdint>
#include <math.h>

#define S_LEN 4096
#define DMODEL 768
#define NHEADS 12
#define DHEAD 64

// Scratch (static device globals — no allocation allowed)
__device__ float g_Qh[NHEADS * S_LEN * DHEAD];   // [h][s][d]
__device__ float g_Kh[NHEADS * S_LEN * DHEAD];
__device__ float g_Vh[NHEADS * S_LEN * DHEAD];
__device__ float g_Ctx[S_LEN * DMODEL];          // [s][dmodel]

// ---------------------------------------------------------------------------
// PTX helpers (sm_80-era PTX only — compute_103 baseline-safe, no tcgen05)
// ---------------------------------------------------------------------------
__device__ __forceinline__ uint32_t smem_u32(const void* p) {
    uint32_t a;
    asm("{ .reg .u64 t; cvta.to.shared.u64 t, %1; cvt.u32.u64 %0, t; }"
        : "=r"(a) : "l"(p));
    return a;
}

#define CP_ASYNC16(dst, src) \
    asm volatile("cp.async.cg.shared.global [%0], [%1], 16;" \
                 :: "r"(dst), "l"(src))
#define CP_COMMIT() asm volatile("cp.async.commit_group;" ::: "memory")
#define CP_WAIT3()  asm volatile("cp.async.wait_group 3;" ::: "memory")
#define CP_WAIT1()  asm volatile("cp.async.wait_group 1;" ::: "memory")
#define CP_WAIT0()  asm volatile("cp.async.wait_group 0;" ::: "memory")

__device__ __forceinline__ void ldsm_x4(uint32_t* r, uint32_t addr) {
    asm volatile("ldmatrix.sync.aligned.m8n8.x4.shared.b16 {%0,%1,%2,%3}, [%4];"
                 : "=r"(r[0]), "=r"(r[1]), "=r"(r[2]), "=r"(r[3]) : "r"(addr));
}
__device__ __forceinline__ void ldsm_x2(uint32_t* r, uint32_t addr) {
    asm volatile("ldmatrix.sync.aligned.m8n8.x2.shared.b16 {%0,%1}, [%2];"
                 : "=r"(r[0]), "=r"(r[1]) : "r"(addr));
}
__device__ __forceinline__ uint32_t f2tf32(uint32_t x) {
    uint32_t o;
    asm("cvt.rna.tf32.f32 %0, %1;" : "=r"(o) : "f"(__uint_as_float(x)));
    return o;
}
__device__ __forceinline__ uint32_t tf32r(float f) {
    uint32_t o;
    asm("cvt.rna.tf32.f32 %0, %1;" : "=r"(o) : "f"(f));
    return o;
}
__device__ __forceinline__ void mma_tf32(float* c, const uint32_t* a, const uint32_t* b) {
    asm volatile(
        "mma.sync.aligned.m16n8k8.row.col.f32.tf32.tf32.f32 "
        "{%0,%1,%2,%3}, {%4,%5,%6,%7}, {%8,%9}, {%0,%1,%2,%3};"
        : "+f"(c[0]), "+f"(c[1]), "+f"(c[2]), "+f"(c[3])
        : "r"(a[0]), "r"(a[1]), "r"(a[2]), "r"(a[3]), "r"(b[0]), "r"(b[1]));
}
__device__ __forceinline__ void lds128f(float4& v, uint32_t a) {
    asm volatile("ld.shared.v4.f32 {%0,%1,%2,%3}, [%4];"
                 : "=f"(v.x), "=f"(v.y), "=f"(v.z), "=f"(v.w) : "r"(a));
}
__device__ __forceinline__ void sts128u(uint32_t a, uint32_t x, uint32_t y,
                                        uint32_t z, uint32_t w) {
    asm volatile("st.shared.v4.b32 [%0], {%1,%2,%3,%4};"
                 :: "r"(a), "r"(x), "r"(y), "r"(z), "r"(w));
}
__device__ __forceinline__ uint32_t lds32(uint32_t a) {
    uint32_t v;
    asm volatile("ld.shared.b32 %0, [%1];" : "=r"(v) : "r"(a));
    return v;
}
__device__ __forceinline__ void sts64u(uint32_t a, uint32_t x, uint32_t y) {
    asm volatile("st.shared.v2.b32 [%0], {%1,%2};" :: "r"(a), "r"(x), "r"(y));
}

// ---------------------------------------------------------------------------
// TF32 tensor-core GEMM (unchanged from round 3 — verified correct)
// ---------------------------------------------------------------------------
#define ROWW 20
#define HALF_STAGE_BYTES (128 * ROWW * 4)
#define STAGE_BYTES (2 * HALF_STAGE_BYTES)
#define NSTAGE 4
#define GEMM_SMEM_BYTES (NSTAGE * STAGE_BYTES)
#define KT_TILES 48

template<int MODE>
__global__ __launch_bounds__(256)
void gemm_mma(const float* __restrict__ A_in, const float* __restrict__ W,
              const float* __restrict__ bias, float* __restrict__ Out)
{
    extern __shared__ float sm[];
    const uint32_t sbase = smem_u32(sm);

    const int tid  = threadIdx.x;
    const int lane = tid & 31;
    const int wid  = tid >> 5;
    const int m0 = blockIdx.y * 128;
    const int n0 = blockIdx.x * 128;
    const int warp_m = (wid & 1) * 64;
    const int warp_n = (wid >> 1) * 32;

    const float* Ag = (MODE == 3) ? (const float*)g_Ctx : A_in;
    const char* gA = (const char*)(Ag + (size_t)m0 * DMODEL);
    const char* gB = (const char*)(W + (size_t)n0 * DMODEL);

    auto issue = [&](int kt) {
        int stage = kt & (NSTAGE - 1);
        uint32_t dstBase = sbase + stage * STAGE_BYTES;
#pragma unroll
        for (int c = 0; c < 4; c++) {
            int idx = tid + c * 256;
            int mat = idx >> 9;
            int i   = idx & 511;
            int row = i >> 2;
            int ch  = i & 3;
            uint32_t dst = dstBase + mat * HALF_STAGE_BYTES + row * (ROWW * 4) + ch * 16;
            const char* src = (mat ? gB : gA) + (size_t)row * 3072 + (size_t)kt * 64 + ch * 16;
            CP_ASYNC16(dst, src);
        }
    };

    float acc[4][4][4];
#pragma unroll
    for (int i = 0; i < 4; i++)
#pragma unroll
        for (int j = 0; j < 4; j++)
#pragma unroll
            for (int r = 0; r < 4; r++) acc[i][j][r] = 0.f;

    issue(0); CP_COMMIT();
    issue(1); CP_COMMIT();
    issue(2); CP_COMMIT();

    const int a_rowoff = ((lane >> 3) & 1) * 8 + (lane & 7);
    const int a_half   = (lane >> 4) & 1;
    const int b_l      = lane & 15;
    const int b_row    = b_l & 7;
    const int b_half   = (b_l >> 3) & 1;

    for (int kt = 0; kt < KT_TILES; kt++) {
        if (kt + 3 < KT_TILES) issue(kt + 3);
        CP_COMMIT();
        CP_WAIT3();
        __syncthreads();

        uint32_t aS = sbase + (kt & (NSTAGE - 1)) * STAGE_BYTES;
        uint32_t bS = aS + HALF_STAGE_BYTES;

#pragma unroll
        for (int ks = 0; ks < 2; ks++) {
            uint32_t a[4][4], b[4][2];
#pragma unroll
            for (int am = 0; am < 4; am++) {
                uint32_t addr = aS + (warp_m + am * 16 + a_rowoff) * (ROWW * 4)
                              + ks * 32 + a_half * 16;
                ldsm_x4(a[am], addr);
            }
#pragma unroll
            for (int bn = 0; bn < 4; bn++) {
                uint32_t addr = bS + (warp_n + bn * 8 + b_row) * (ROWW * 4)
                              + ks * 32 + b_half * 16;
                ldsm_x2(b[bn], addr);
            }
#pragma unroll
            for (int am = 0; am < 4; am++)
#pragma unroll
                for (int j = 0; j < 4; j++) a[am][j] = f2tf32(a[am][j]);
#pragma unroll
            for (int bn = 0; bn < 4; bn++) {
                b[bn][0] = f2tf32(b[bn][0]);
                b[bn][1] = f2tf32(b[bn][1]);
            }
#pragma unroll
            for (int am = 0; am < 4; am++)
#pragma unroll
                for (int bn = 0; bn < 4; bn++)
                    mma_tf32(acc[am][bn], a[am], b[bn]);
        }
        __syncthreads();
    }

    const int g   = lane >> 2;
    const int tig = lane & 3;
#pragma unroll
    for (int am = 0; am < 4; am++) {
#pragma unroll
        for (int bn = 0; bn < 4; bn++) {
            int ncol = n0 + warp_n + bn * 8 + tig * 2;
            float2 bz = *(const float2*)(bias + ncol);
#pragma unroll
            for (int h = 0; h < 2; h++) {
                int m = m0 + warp_m + am * 16 + g + h * 8;
                float2 o;
                o.x = acc[am][bn][h * 2 + 0] + bz.x;
                o.y = acc[am][bn][h * 2 + 1] + bz.y;
                if (MODE == 3) {
                    *(float2*)(Out + (size_t)m * DMODEL + ncol) = o;
                } else {
                    int hd = ncol >> 6;
                    int d  = ncol & 63;
                    float* base = (MODE == 0) ? g_Qh : (MODE == 1) ? g_Kh : g_Vh;
                    *(float2*)(base + ((size_t)hd * S_LEN + m) * DHEAD + d) = o;
                }
            }
        }
    }
}

// ---------------------------------------------------------------------------
// Tensor-core flash attention (causal, tf32 mma with QK error compensation).
// BM=128 q rows/CTA, BN=64 keys/iter, 8 warps (warp w owns q rows 16w..16w+15).
// K: natural [key][d] rows pad-68w (ldsm B-frags, split hi/lo in smem).
// V: natural [key][d] rows pad-72w (LDS.32 B-frags, conflict-free, tf32-rounded).
// P: staged via warp-private smem rows pad-68w, read back with ldmatrix.
// ---------------------------------------------------------------------------
#define KS_ROWB 272                     // 68 words
#define VN_ROWB 288                     // 72 words
#define PS_ROWB 272
#define KS_STG  (64 * KS_ROWB)          // 17408
#define VN_STG  (64 * VN_ROWB)          // 18432
#define OFF_KS0 0
#define OFF_KS1 (OFF_KS0 + KS_STG)
#define OFF_VN0 (OFF_KS1 + KS_STG)
#define OFF_VN1 (OFF_VN0 + VN_STG)
#define OFF_KL  (OFF_VN1 + VN_STG)
#define OFF_PS  (OFF_KL + KS_STG)
#define ATTN_SMEM_BYTES (OFF_PS + 128 * PS_ROWB)   // 123904

__global__ __launch_bounds__(256, 1)
void flash_attn_mma()
{
    extern __shared__ char smc[];
    const uint32_t sb = smem_u32(smc);
    const int tid  = threadIdx.x;
    const int lane = tid & 31;
    const int w    = tid >> 5;
    const int head = blockIdx.y;
    const int qb   = gridDim.x - 1 - blockIdx.x;   // biggest workload first
    const int q0   = qb * 128;

    const float* Qg = g_Qh + (size_t)head * S_LEN * DHEAD;
    const float* Kg = g_Kh + (size_t)head * S_LEN * DHEAD;
    const float* Vg = g_Vh + (size_t)head * S_LEN * DHEAD;

    // ---- Q prologue: stage to smem (Ps region), load + scale + split frags ----
#pragma unroll
    for (int p = 0; p < 8; p++) {
        int e   = tid + p * 256;          // 0..2047
        int row = e >> 4;                 // 0..127
        int c4  = e & 15;
        float4 v = *(const float4*)(Qg + (size_t)(q0 + row) * DHEAD + c4 * 4);
        sts128u(sb + OFF_PS + row * PS_ROWB + c4 * 16,
                __float_as_uint(v.x), __float_as_uint(v.y),
                __float_as_uint(v.z), __float_as_uint(v.w));
    }
    __syncthreads();

    const int a_rowoff = ((lane >> 3) & 1) * 8 + (lane & 7);
    const int a_half   = (lane >> 4) & 1;
    const uint32_t aAddrBase = sb + OFF_PS + (w * 16 + a_rowoff) * PS_ROWB + a_half * 16;

    uint32_t qh[8][4], ql[8][4];
#pragma unroll
    for (int kb = 0; kb < 8; kb++) {
        uint32_t t4[4];
        ldsm_x4(t4, aAddrBase + kb * 32);
#pragma unroll
        for (int j = 0; j < 4; j++) {
            float v = 0.125f * __uint_as_float(t4[j]);   // fold 1/sqrt(64)
            qh[kb][j] = tf32r(v);
            ql[kb][j] = tf32r(v - __uint_as_float(qh[kb][j]));
        }
    }
    // Ps rows are warp-private from here on (each warp reads/writes rows 16w..16w+15)

    float m_[2] = {-1e30f, -1e30f};
    float l_[2] = {0.f, 0.f};
    float o[8][4];
#pragma unroll
    for (int nb = 0; nb < 8; nb++)
#pragma unroll
        for (int j = 0; j < 4; j++) o[nb][j] = 0.f;

    // cp.async issue of one K/V tile (2048 16B chunks over 256 threads)
    auto issue = [&](int t) {
        uint32_t ksB = sb + ((t & 1) ? OFF_KS1 : OFF_KS0);
        uint32_t vnB = sb + ((t & 1) ? OFF_VN1 : OFF_VN0);
        int kv0 = t * 64;
#pragma unroll
        for (int c = 0; c < 8; c++) {
            int i   = tid + c * 256;      // 0..2047
            int mat = i >> 10;            // 0: K, 1: V
            int j   = i & 1023;
            int row = j >> 4;
            int ch  = j & 15;
            const char* src = (const char*)((mat ? Vg : Kg) + (size_t)(kv0 + row) * DHEAD)
                            + ch * 16;
            uint32_t dst = mat ? (vnB + row * VN_ROWB + ch * 16)
                               : (ksB + row * KS_ROWB + ch * 16);
            CP_ASYNC16(dst, src);
        }
    };

    issue(0); CP_COMMIT();

    const int b_nboff = ((lane >> 4) & 1) * 8;
    const int b_row   = lane & 7;
    const int b_half  = (lane >> 3) & 1;
    const int g       = lane >> 2;
    const int tg      = lane & 3;
    const int ntiles  = 2 * qb + 2;

    for (int t = 0; t < ntiles; t++) {
        if (t + 1 < ntiles) { issue(t + 1); CP_COMMIT(); CP_WAIT1(); }
        else                { CP_WAIT0(); }
        __syncthreads();

        uint32_t ksS = sb + ((t & 1) ? OFF_KS1 : OFF_KS0);
        uint32_t vnS = sb + ((t & 1) ? OFF_VN1 : OFF_VN0);

        // Cooperative pass: split K -> hi(in place)/lo(KL); round V to tf32 in place
#pragma unroll
        for (int p = 0; p < 4; p++) {
            int e   = tid + p * 256;      // 0..1023
            int row = e >> 4;
            int c4  = e & 15;
            uint32_t ka = ksS + row * KS_ROWB + c4 * 16;
            float4 v; lds128f(v, ka);
            uint32_t hx = tf32r(v.x), hy = tf32r(v.y), hz = tf32r(v.z), hw = tf32r(v.w);
            sts128u(ka, hx, hy, hz, hw);
            sts128u(sb + OFF_KL + row * KS_ROWB + c4 * 16,
                    tf32r(v.x - __uint_as_float(hx)), tf32r(v.y - __uint_as_float(hy)),
                    tf32r(v.z - __uint_as_float(hz)), tf32r(v.w - __uint_as_float(hw)));
            uint32_t va = vnS + row * VN_ROWB + c4 * 16;
            float4 vv; lds128f(vv, va);
            sts128u(va, tf32r(vv.x), tf32r(vv.y), tf32r(vv.z), tf32r(vv.w));
        }
        __syncthreads();

        // ---- S = (Q*scale) K^T with 3-term tf32 compensation ----
        float s[8][4];
#pragma unroll
        for (int nb = 0; nb < 8; nb++)
#pragma unroll
            for (int j = 0; j < 4; j++) s[nb][j] = 0.f;

#pragma unroll
        for (int kb = 0; kb < 8; kb++) {
            uint32_t bh[16], bl[16];
#pragma unroll
            for (int bp = 0; bp < 4; bp++) {
                uint32_t roff = (bp * 16 + b_nboff + b_row) * KS_ROWB + kb * 32 + b_half * 16;
                ldsm_x4(&bh[bp * 4], ksS + roff);
                ldsm_x4(&bl[bp * 4], sb + OFF_KL + roff);
            }
#pragma unroll
            for (int nb = 0; nb < 8; nb++) {
                mma_tf32(s[nb], qh[kb], &bh[nb * 2]);
                mma_tf32(s[nb], ql[kb], &bh[nb * 2]);
                mma_tf32(s[nb], qh[kb], &bl[nb * 2]);
            }
        }

        // ---- causal mask (only last two tiles) ----
        const int kv0 = t * 64;
        if (t >= 2 * qb) {
            int qa = q0 + w * 16 + g;
#pragma unroll
            for (int nb = 0; nb < 8; nb++) {
#pragma unroll
                for (int j = 0; j < 4; j++) {
                    int col = kv0 + nb * 8 + 2 * tg + (j & 1);
                    int row = qa + (j >> 1) * 8;
                    if (col > row) s[nb][j] = -1e30f;
                }
            }
        }

        // ---- online softmax on fragments (rows g and g+8) ----
#pragma unroll
        for (int r = 0; r < 2; r++) {
            float mx = m_[r];
#pragma unroll
            for (int nb = 0; nb < 8; nb++)
                mx = fmaxf(mx, fmaxf(s[nb][2 * r], s[nb][2 * r + 1]));
            mx = fmaxf(mx, __shfl_xor_sync(0xffffffffu, mx, 1));
            mx = fmaxf(mx, __shfl_xor_sync(0xffffffffu, mx, 2));
            float esc = __expf(m_[r] - mx);
            float sum = 0.f;
#pragma unroll
            for (int nb = 0; nb < 8; nb++) {
#pragma unroll
                for (int jj = 0; jj < 2; jj++) {
                    float p = __expf(s[nb][2 * r + jj] - mx);
                    uint32_t pr = tf32r(p);           // round BEFORE summing
                    s[nb][2 * r + jj] = __uint_as_float(pr);
                    sum += __uint_as_float(pr);
                }
            }
            sum += __shfl_xor_sync(0xffffffffu, sum, 1);
            sum += __shfl_xor_sync(0xffffffffu, sum, 2);
            l_[r] = l_[r] * esc + sum;
            m_[r] = mx;
#pragma unroll
            for (int nb = 0; nb < 8; nb++) {
                o[nb][2 * r]     *= esc;
                o[nb][2 * r + 1] *= esc;
            }
        }

        // ---- store P (tf32-valued) to warp-private Ps rows ----
        uint32_t psW = sb + OFF_PS + (w * 16 + g) * PS_ROWB + tg * 8;
#pragma unroll
        for (int nb = 0; nb < 8; nb++) {
            sts64u(psW + nb * 32,
                   __float_as_uint(s[nb][0]), __float_as_uint(s[nb][1]));
            sts64u(psW + 8 * PS_ROWB + nb * 32,
                   __float_as_uint(s[nb][2]), __float_as_uint(s[nb][3]));
        }
        __syncwarp();

        // ---- O += P V ----
#pragma unroll
        for (int kb = 0; kb < 8; kb++) {
            uint32_t pa[4];
            ldsm_x4(pa, aAddrBase + kb * 32);
            uint32_t vrow0 = vnS + (kb * 8 + tg) * VN_ROWB + (lane >> 2) * 4;
#pragma unroll
            for (int nb = 0; nb < 8; nb++) {
                uint32_t bb[2];
                bb[0] = lds32(vrow0 + nb * 32);
                bb[1] = lds32(vrow0 + 4 * VN_ROWB + nb * 32);
                mma_tf32(o[nb], pa, bb);
            }
        }
        __syncthreads();   // protect Ks/Kl/Vn before next tile's overwrite
    }

    // ---- epilogue: normalize, write context [s][dmodel] ----
#pragma unroll
    for (int r = 0; r < 2; r++) {
        float inv = 1.f / l_[r];
        int qrow = q0 + w * 16 + g + r * 8;
        float* dst = g_Ctx + (size_t)qrow * DMODEL + head * DHEAD + 2 * tg;
#pragma unroll
        for (int nb = 0; nb < 8; nb++) {
            float2 ov;
            ov.x = o[nb][2 * r]     * inv;
            ov.y = o[nb][2 * r + 1] * inv;
            *(float2*)(dst + nb * 8) = ov;
        }
    }
}

// ---------------------------------------------------------------------------
extern "C" void kernel_launch(void* const* d_in, const int* in_sizes, int n_in,
                              void* d_out, int out_size)
{
    const float* q  = (const float*)d_in[0];
    const float* k  = (const float*)d_in[1];
    const float* v  = (const float*)d_in[2];
    const float* wq = (const float*)d_in[3];
    const float* bq = (const float*)d_in[4];
    const float* wk = (const float*)d_in[5];
    const float* bk = (const float*)d_in[6];
    const float* wv = (const float*)d_in[7];
    const float* bv = (const float*)d_in[8];
    const float* wo = (const float*)d_in[9];
    const float* bo = (const float*)d_in[10];
    float* out = (float*)d_out;

    cudaFuncSetAttribute(gemm_mma<0>, cudaFuncAttributeMaxDynamicSharedMemorySize, GEMM_SMEM_BYTES);
    cudaFuncSetAttribute(gemm_mma<1>, cudaFuncAttributeMaxDynamicSharedMemorySize, GEMM_SMEM_BYTES);
    cudaFuncSetAttribute(gemm_mma<2>, cudaFuncAttributeMaxDynamicSharedMemorySize, GEMM_SMEM_BYTES);
    cudaFuncSetAttribute(gemm_mma<3>, cudaFuncAttributeMaxDynamicSharedMemorySize, GEMM_SMEM_BYTES);
    cudaFuncSetAttribute(flash_attn_mma, cudaFuncAttributeMaxDynamicSharedMemorySize, ATTN_SMEM_BYTES);

    dim3 gg(DMODEL / 128, S_LEN / 128);   // (6, 32)

    gemm_mma<0><<<gg, 256, GEMM_SMEM_BYTES>>>(q, wq, bq, nullptr);
    gemm_mma<1><<<gg, 256, GEMM_SMEM_BYTES>>>(k, wk, bk, nullptr);
    gemm_mma<2><<<gg, 256, GEMM_SMEM_BYTES>>>(v, wv, bv, nullptr);

    flash_attn_mma<<<dim3(S_LEN / 128, NHEADS), 256, ATTN_SMEM_BYTES>>>();

    gemm_mma<3><<<gg, 256, GEMM_SMEM_BYTES>>>(nullptr, wo, bo, out);
}

// round 5
// speedup vs baseline: 3.5105x; 1.3007x over previous
#include <cuda_runtime.h>
#include <cstdint>
#include <math.h>

#define S_LEN 4096
#define DMODEL 768
#define NHEADS 12
#define DHEAD 64

// Scratch (static device globals — no allocation allowed)
__device__ float g_Qh[NHEADS * S_LEN * DHEAD];   // [h][s][d]  (raw fp32)
__device__ float g_Kh[NHEADS * S_LEN * DHEAD];   // [h][s][d]  (tf32-rounded)
__device__ float g_Vt[NHEADS * DHEAD * S_LEN];   // [h][d][s]  (tf32-rounded, transposed)
__device__ float g_Ctx[S_LEN * DMODEL];          // [s][dmodel]

// ---------------------------------------------------------------------------
// PTX helpers (sm_80-era PTX only — compute_103 baseline-safe)
// ---------------------------------------------------------------------------
__device__ __forceinline__ uint32_t smem_u32(const void* p) {
    uint32_t a;
    asm("{ .reg .u64 t; cvta.to.shared.u64 t, %1; cvt.u32.u64 %0, t; }"
        : "=r"(a) : "l"(p));
    return a;
}

#define CP_ASYNC16(dst, src) \
    asm volatile("cp.async.cg.shared.global [%0], [%1], 16;" \
                 :: "r"(dst), "l"(src))
#define CP_COMMIT() asm volatile("cp.async.commit_group;" ::: "memory")
#define CP_WAIT3()  asm volatile("cp.async.wait_group 3;" ::: "memory")
#define CP_WAIT1()  asm volatile("cp.async.wait_group 1;" ::: "memory")
#define CP_WAIT0()  asm volatile("cp.async.wait_group 0;" ::: "memory")

__device__ __forceinline__ void ldsm_x4(uint32_t* r, uint32_t addr) {
    asm volatile("ldmatrix.sync.aligned.m8n8.x4.shared.b16 {%0,%1,%2,%3}, [%4];"
                 : "=r"(r[0]), "=r"(r[1]), "=r"(r[2]), "=r"(r[3]) : "r"(addr));
}
__device__ __forceinline__ void ldsm_x2(uint32_t* r, uint32_t addr) {
    asm volatile("ldmatrix.sync.aligned.m8n8.x2.shared.b16 {%0,%1}, [%2];"
                 : "=r"(r[0]), "=r"(r[1]) : "r"(addr));
}
__device__ __forceinline__ uint32_t f2tf32(uint32_t x) {
    uint32_t o;
    asm("cvt.rna.tf32.f32 %0, %1;" : "=r"(o) : "f"(__uint_as_float(x)));
    return o;
}
__device__ __forceinline__ uint32_t tf32r(float f) {
    uint32_t o;
    asm("cvt.rna.tf32.f32 %0, %1;" : "=r"(o) : "f"(f));
    return o;
}
__device__ __forceinline__ float tf32rf(float f) {
    return __uint_as_float(tf32r(f));
}
__device__ __forceinline__ void mma_tf32(float* c, const uint32_t* a, const uint32_t* b) {
    asm volatile(
        "mma.sync.aligned.m16n8k8.row.col.f32.tf32.tf32.f32 "
        "{%0,%1,%2,%3}, {%4,%5,%6,%7}, {%8,%9}, {%0,%1,%2,%3};"
        : "+f"(c[0]), "+f"(c[1]), "+f"(c[2]), "+f"(c[3])
        : "r"(a[0]), "r"(a[1]), "r"(a[2]), "r"(a[3]), "r"(b[0]), "r"(b[1]));
}
__device__ __forceinline__ void sts128u(uint32_t a, uint32_t x, uint32_t y,
                                        uint32_t z, uint32_t w) {
    asm volatile("st.shared.v4.b32 [%0], {%1,%2,%3,%4};"
                 :: "r"(a), "r"(x), "r"(y), "r"(z), "r"(w));
}
__device__ __forceinline__ void sts64u(uint32_t a, uint32_t x, uint32_t y) {
    asm volatile("st.shared.v2.b32 [%0], {%1,%2};" :: "r"(a), "r"(x), "r"(y));
}

// ---------------------------------------------------------------------------
// TF32 tensor-core GEMM body (shared by fused-QKV and O-proj kernels).
// Tile 128x128, BK=16, 256 threads (8 warps 2m x 4n, each 64x32), 4-stage
// cp.async, rows padded to 20 words (bank-conflict-free LDSM).
// ---------------------------------------------------------------------------
#define ROWW 20
#define HALF_STAGE_BYTES (128 * ROWW * 4)
#define STAGE_BYTES (2 * HALF_STAGE_BYTES)
#define NSTAGE 4
#define GEMM_SMEM_BYTES (NSTAGE * STAGE_BYTES)
#define KT_TILES 48

struct GemmFrag {
    float acc[4][4][4];
};

__device__ __forceinline__ void gemm_core(const float* __restrict__ A,
                                          const float* __restrict__ W,
                                          int m0, int n0, GemmFrag& F)
{
    extern __shared__ float sm[];
    const uint32_t sbase = smem_u32(sm);
    const int tid  = threadIdx.x;
    const int lane = tid & 31;
    const int wid  = tid >> 5;
    const int warp_m = (wid & 1) * 64;
    const int warp_n = (wid >> 1) * 32;

    const char* gA = (const char*)(A + (size_t)m0 * DMODEL);
    const char* gB = (const char*)(W + (size_t)n0 * DMODEL);

    auto issue = [&](int kt) {
        int stage = kt & (NSTAGE - 1);
        uint32_t dstBase = sbase + stage * STAGE_BYTES;
#pragma unroll
        for (int c = 0; c < 4; c++) {
            int idx = tid + c * 256;
            int mat = idx >> 9;
            int i   = idx & 511;
            int row = i >> 2;
            int ch  = i & 3;
            uint32_t dst = dstBase + mat * HALF_STAGE_BYTES + row * (ROWW * 4) + ch * 16;
            const char* src = (mat ? gB : gA) + (size_t)row * 3072 + (size_t)kt * 64 + ch * 16;
            CP_ASYNC16(dst, src);
        }
    };

#pragma unroll
    for (int i = 0; i < 4; i++)
#pragma unroll
        for (int j = 0; j < 4; j++)
#pragma unroll
            for (int r = 0; r < 4; r++) F.acc[i][j][r] = 0.f;

    issue(0); CP_COMMIT();
    issue(1); CP_COMMIT();
    issue(2); CP_COMMIT();

    const int a_rowoff = ((lane >> 3) & 1) * 8 + (lane & 7);
    const int a_half   = (lane >> 4) & 1;
    const int b_l      = lane & 15;
    const int b_row    = b_l & 7;
    const int b_half   = (b_l >> 3) & 1;

    for (int kt = 0; kt < KT_TILES; kt++) {
        if (kt + 3 < KT_TILES) issue(kt + 3);
        CP_COMMIT();
        CP_WAIT3();
        __syncthreads();

        uint32_t aS = sbase + (kt & (NSTAGE - 1)) * STAGE_BYTES;
        uint32_t bS = aS + HALF_STAGE_BYTES;

#pragma unroll
        for (int ks = 0; ks < 2; ks++) {
            uint32_t a[4][4], b[4][2];
#pragma unroll
            for (int am = 0; am < 4; am++) {
                uint32_t addr = aS + (warp_m + am * 16 + a_rowoff) * (ROWW * 4)
                              + ks * 32 + a_half * 16;
                ldsm_x4(a[am], addr);
            }
#pragma unroll
            for (int bn = 0; bn < 4; bn++) {
                uint32_t addr = bS + (warp_n + bn * 8 + b_row) * (ROWW * 4)
                              + ks * 32 + b_half * 16;
                ldsm_x2(b[bn], addr);
            }
#pragma unroll
            for (int am = 0; am < 4; am++)
#pragma unroll
                for (int j = 0; j < 4; j++) a[am][j] = f2tf32(a[am][j]);
#pragma unroll
            for (int bn = 0; bn < 4; bn++) {
                b[bn][0] = f2tf32(b[bn][0]);
                b[bn][1] = f2tf32(b[bn][1]);
            }
#pragma unroll
            for (int am = 0; am < 4; am++)
#pragma unroll
                for (int bn = 0; bn < 4; bn++)
                    mma_tf32(F.acc[am][bn], a[am], b[bn]);
        }
        __syncthreads();
    }
}

// Fused Q/K/V projections. blockIdx.z selects which projection.
// z=0: Q -> g_Qh raw. z=1: K -> g_Kh tf32-rounded. z=2: V -> g_Vt transposed+rounded.
__global__ __launch_bounds__(256)
void gemm_qkv(const float* __restrict__ q, const float* __restrict__ k,
              const float* __restrict__ v,
              const float* __restrict__ wq, const float* __restrict__ bq,
              const float* __restrict__ wk, const float* __restrict__ bk,
              const float* __restrict__ wv, const float* __restrict__ bv)
{
    const int z = blockIdx.z;
    const float* A    = (z == 0) ? q  : (z == 1) ? k  : v;
    const float* W    = (z == 0) ? wq : (z == 1) ? wk : wv;
    const float* bias = (z == 0) ? bq : (z == 1) ? bk : bv;

    const int m0 = blockIdx.y * 128;
    const int n0 = blockIdx.x * 128;

    GemmFrag F;
    gemm_core(A, W, m0, n0, F);

    const int lane = threadIdx.x & 31;
    const int wid  = threadIdx.x >> 5;
    const int warp_m = (wid & 1) * 64;
    const int warp_n = (wid >> 1) * 32;
    const int g   = lane >> 2;
    const int tig = lane & 3;

#pragma unroll
    for (int am = 0; am < 4; am++) {
#pragma unroll
        for (int bn = 0; bn < 4; bn++) {
            int ncol = n0 + warp_n + bn * 8 + tig * 2;
            float2 bz = *(const float2*)(bias + ncol);
            int hd = ncol >> 6;
            int d  = ncol & 63;
#pragma unroll
            for (int h = 0; h < 2; h++) {
                int m = m0 + warp_m + am * 16 + g + h * 8;
                float ox = F.acc[am][bn][h * 2 + 0] + bz.x;
                float oy = F.acc[am][bn][h * 2 + 1] + bz.y;
                if (z == 0) {
                    float2 o = make_float2(ox, oy);
                    *(float2*)(g_Qh + ((size_t)hd * S_LEN + m) * DHEAD + d) = o;
                } else if (z == 1) {
                    float2 o = make_float2(tf32rf(ox), tf32rf(oy));
                    *(float2*)(g_Kh + ((size_t)hd * S_LEN + m) * DHEAD + d) = o;
                } else {
                    g_Vt[((size_t)hd * DHEAD + d)     * S_LEN + m] = tf32rf(ox);
                    g_Vt[((size_t)hd * DHEAD + d + 1) * S_LEN + m] = tf32rf(oy);
                }
            }
        }
    }
}

// Output projection: g_Ctx @ wo^T + bo -> out
__global__ __launch_bounds__(256)
void gemm_out(const float* __restrict__ wo, const float* __restrict__ bo,
              float* __restrict__ Out)
{
    const int m0 = blockIdx.y * 128;
    const int n0 = blockIdx.x * 128;

    GemmFrag F;
    gemm_core((const float*)g_Ctx, wo, m0, n0, F);

    const int lane = threadIdx.x & 31;
    const int wid  = threadIdx.x >> 5;
    const int warp_m = (wid & 1) * 64;
    const int warp_n = (wid >> 1) * 32;
    const int g   = lane >> 2;
    const int tig = lane & 3;

#pragma unroll
    for (int am = 0; am < 4; am++) {
#pragma unroll
        for (int bn = 0; bn < 4; bn++) {
            int ncol = n0 + warp_n + bn * 8 + tig * 2;
            float2 bz = *(const float2*)(bo + ncol);
#pragma unroll
            for (int h = 0; h < 2; h++) {
                int m = m0 + warp_m + am * 16 + g + h * 8;
                float2 o;
                o.x = F.acc[am][bn][h * 2 + 0] + bz.x;
                o.y = F.acc[am][bn][h * 2 + 1] + bz.y;
                *(float2*)(Out + (size_t)m * DMODEL + ncol) = o;
            }
        }
    }
}

// ---------------------------------------------------------------------------
// Tensor-core flash attention (causal), 2-term tf32 QK (Q split hi/lo in regs,
// K pre-rounded at producer). BM=64 q rows/CTA, BN=64 keys/iter, 128 threads
// (4 warps, warp w owns q rows 16w..16w+15). V pre-transposed+rounded ->
// PV B-fragments via ldmatrix. 87KB smem -> 2 CTAs/SM.
// ---------------------------------------------------------------------------
#define KS_ROWB 272                     // 68 words (mod 32 = 4: conflict-free ldsm)
#define VT_ROWB 272
#define PS_ROWB 272
#define KS_STG  (64 * KS_ROWB)          // 17408
#define VT_STG  (64 * VT_ROWB)
#define OFF_KS0 0
#define OFF_KS1 (OFF_KS0 + KS_STG)
#define OFF_VT0 (OFF_KS1 + KS_STG)
#define OFF_VT1 (OFF_VT0 + VT_STG)
#define OFF_PS  (OFF_VT1 + VT_STG)
#define ATTN_SMEM_BYTES (OFF_PS + 64 * PS_ROWB)    // 87040

__global__ __launch_bounds__(128)
void flash_attn_mma()
{
    extern __shared__ char smc[];
    const uint32_t sb = smem_u32(smc);
    const int tid  = threadIdx.x;
    const int lane = tid & 31;
    const int w    = tid >> 5;          // 0..3
    const int head = blockIdx.y;
    const int qb   = gridDim.x - 1 - blockIdx.x;   // biggest workload first
    const int q0   = qb * 64;

    const float* Qg = g_Qh + (size_t)head * S_LEN * DHEAD;
    const float* Kg = g_Kh + (size_t)head * S_LEN * DHEAD;
    const float* Vt = g_Vt + (size_t)head * DHEAD * S_LEN;

    // ---- Q prologue: stage rows to smem, then build scaled hi/lo fragments ----
#pragma unroll
    for (int p = 0; p < 8; p++) {
        int e   = tid + p * 128;          // 0..1023
        int row = e >> 4;                 // 0..63
        int c4  = e & 15;
        float4 v = *(const float4*)(Qg + (size_t)(q0 + row) * DHEAD + c4 * 4);
        sts128u(sb + OFF_PS + row * PS_ROWB + c4 * 16,
                __float_as_uint(v.x), __float_as_uint(v.y),
                __float_as_uint(v.z), __float_as_uint(v.w));
    }
    __syncthreads();

    const int a_rowoff = ((lane >> 3) & 1) * 8 + (lane & 7);
    const int a_half   = (lane >> 4) & 1;
    const uint32_t aAddrBase = sb + OFF_PS + (w * 16 + a_rowoff) * PS_ROWB + a_half * 16;

    uint32_t qh[8][4], ql[8][4];
#pragma unroll
    for (int kb = 0; kb < 8; kb++) {
        uint32_t t4[4];
        ldsm_x4(t4, aAddrBase + kb * 32);
#pragma unroll
        for (int j = 0; j < 4; j++) {
            float v = 0.125f * __uint_as_float(t4[j]);   // fold 1/sqrt(64)
            qh[kb][j] = tf32r(v);
            ql[kb][j] = tf32r(v - __uint_as_float(qh[kb][j]));
        }
    }
    // From here Ps rows 16w..16w+15 are warp-private (P staging).

    float m_[2] = {-1e30f, -1e30f};
    float l_[2] = {0.f, 0.f};
    float o[8][4];
#pragma unroll
    for (int nb = 0; nb < 8; nb++)
#pragma unroll
        for (int j = 0; j < 4; j++) o[nb][j] = 0.f;

    // cp.async one K + V^T tile (2048 16B chunks over 128 threads)
    auto issue = [&](int t) {
        uint32_t ksB = sb + ((t & 1) ? OFF_KS1 : OFF_KS0);
        uint32_t vtB = sb + ((t & 1) ? OFF_VT1 : OFF_VT0);
        int kv0 = t * 64;
#pragma unroll
        for (int c = 0; c < 16; c++) {
            int i   = tid + c * 128;      // 0..2047
            int mat = i >> 10;            // 0: K, 1: V^T
            int j   = i & 1023;
            int row = j >> 4;             // 0..63
            int ch  = j & 15;
            if (mat == 0) {
                CP_ASYNC16(ksB + row * KS_ROWB + ch * 16,
                           (const char*)(Kg + (size_t)(kv0 + row) * DHEAD) + ch * 16);
            } else {
                CP_ASYNC16(vtB + row * VT_ROWB + ch * 16,
                           (const char*)(Vt + (size_t)row * S_LEN + kv0) + ch * 16);
            }
        }
    };

    issue(0); CP_COMMIT();

    const int b_nboff = ((lane >> 4) & 1) * 8;
    const int b_l     = lane & 15;
    const int b_row   = b_l & 7;
    const int b_half  = (b_l >> 3) & 1;
    const int g       = lane >> 2;
    const int tg      = lane & 3;
    const int ntiles  = qb + 1;

    for (int t = 0; t < ntiles; t++) {
        if (t + 1 < ntiles) { issue(t + 1); CP_COMMIT(); CP_WAIT1(); }
        else                { CP_WAIT0(); }
        __syncthreads();

        uint32_t ksS = sb + ((t & 1) ? OFF_KS1 : OFF_KS0);
        uint32_t vtS = sb + ((t & 1) ? OFF_VT1 : OFF_VT0);

        // ---- S = (Q*scale) K^T : 2-term tf32 (qh + ql) x pre-rounded K ----
        float s[8][4];
#pragma unroll
        for (int nb = 0; nb < 8; nb++)
#pragma unroll
            for (int j = 0; j < 4; j++) s[nb][j] = 0.f;

#pragma unroll
        for (int kb = 0; kb < 8; kb++) {
            uint32_t bh[16];
#pragma unroll
            for (int bp = 0; bp < 4; bp++) {
                uint32_t roff = (bp * 16 + b_nboff + b_row) * KS_ROWB + kb * 32 + b_half * 16;
                ldsm_x4(&bh[bp * 4], ksS + roff);
            }
#pragma unroll
            for (int nb = 0; nb < 8; nb++) {
                mma_tf32(s[nb], qh[kb], &bh[nb * 2]);
                mma_tf32(s[nb], ql[kb], &bh[nb * 2]);
            }
        }

        // ---- causal mask (diagonal tile only) ----
        if (t == qb) {
            int kv0 = t * 64;
            int qa = q0 + w * 16 + g;
#pragma unroll
            for (int nb = 0; nb < 8; nb++) {
#pragma unroll
                for (int j = 0; j < 4; j++) {
                    int col = kv0 + nb * 8 + 2 * tg + (j & 1);
                    int row = qa + (j >> 1) * 8;
                    if (col > row) s[nb][j] = -1e30f;
                }
            }
        }

        // ---- online softmax on fragments (rows g and g+8) ----
#pragma unroll
        for (int r = 0; r < 2; r++) {
            float mx = m_[r];
#pragma unroll
            for (int nb = 0; nb < 8; nb++)
                mx = fmaxf(mx, fmaxf(s[nb][2 * r], s[nb][2 * r + 1]));
            mx = fmaxf(mx, __shfl_xor_sync(0xffffffffu, mx, 1));
            mx = fmaxf(mx, __shfl_xor_sync(0xffffffffu, mx, 2));
            float esc = __expf(m_[r] - mx);
            float sum = 0.f;
#pragma unroll
            for (int nb = 0; nb < 8; nb++) {
#pragma unroll
                for (int jj = 0; jj < 2; jj++) {
                    float p = __expf(s[nb][2 * r + jj] - mx);
                    uint32_t pr = tf32r(p);            // round BEFORE summing
                    s[nb][2 * r + jj] = __uint_as_float(pr);
                    sum += __uint_as_float(pr);
                }
            }
            sum += __shfl_xor_sync(0xffffffffu, sum, 1);
            sum += __shfl_xor_sync(0xffffffffu, sum, 2);
            l_[r] = l_[r] * esc + sum;
            m_[r] = mx;
#pragma unroll
            for (int nb = 0; nb < 8; nb++) {
                o[nb][2 * r]     *= esc;
                o[nb][2 * r + 1] *= esc;
            }
        }

        // ---- stage P (tf32 values) in warp-private Ps rows ----
        uint32_t psW = sb + OFF_PS + (w * 16 + g) * PS_ROWB + tg * 8;
#pragma unroll
        for (int nb = 0; nb < 8; nb++) {
            sts64u(psW + nb * 32,
                   __float_as_uint(s[nb][0]), __float_as_uint(s[nb][1]));
            sts64u(psW + 8 * PS_ROWB + nb * 32,
                   __float_as_uint(s[nb][2]), __float_as_uint(s[nb][3]));
        }
        __syncwarp();

        // ---- O += P V  (B-fragments from transposed V via ldmatrix) ----
#pragma unroll
        for (int kb = 0; kb < 8; kb++) {
            uint32_t pa[4];
            ldsm_x4(pa, aAddrBase + kb * 32);
#pragma unroll
            for (int nb = 0; nb < 8; nb++) {
                uint32_t bb[2];
                ldsm_x2(bb, vtS + (nb * 8 + b_row) * VT_ROWB + kb * 32 + b_half * 16);
                mma_tf32(o[nb], pa, bb);
            }
        }
        __syncthreads();   // all warps done with buffers before next overwrite
    }

    // ---- epilogue: normalize, write context [s][dmodel] ----
#pragma unroll
    for (int r = 0; r < 2; r++) {
        float inv = 1.f / l_[r];
        int qrow = q0 + w * 16 + g + r * 8;
        float* dst = g_Ctx + (size_t)qrow * DMODEL + head * DHEAD + 2 * tg;
#pragma unroll
        for (int nb = 0; nb < 8; nb++) {
            float2 ov;
            ov.x = o[nb][2 * r]     * inv;
            ov.y = o[nb][2 * r + 1] * inv;
            *(float2*)(dst + nb * 8) = ov;
        }
    }
}

// ---------------------------------------------------------------------------
extern "C" void kernel_launch(void* const* d_in, const int* in_sizes, int n_in,
                              void* d_out, int out_size)
{
    const float* q  = (const float*)d_in[0];
    const float* k  = (const float*)d_in[1];
    const float* v  = (const float*)d_in[2];
    const float* wq = (const float*)d_in[3];
    const float* bq = (const float*)d_in[4];
    const float* wk = (const float*)d_in[5];
    const float* bk = (const float*)d_in[6];
    const float* wv = (const float*)d_in[7];
    const float* bv = (const float*)d_in[8];
    const float* wo = (const float*)d_in[9];
    const float* bo = (const float*)d_in[10];
    float* out = (float*)d_out;

    cudaFuncSetAttribute(gemm_qkv, cudaFuncAttributeMaxDynamicSharedMemorySize, GEMM_SMEM_BYTES);
    cudaFuncSetAttribute(gemm_out, cudaFuncAttributeMaxDynamicSharedMemorySize, GEMM_SMEM_BYTES);
    cudaFuncSetAttribute(flash_attn_mma, cudaFuncAttributeMaxDynamicSharedMemorySize, ATTN_SMEM_BYTES);

    gemm_qkv<<<dim3(DMODEL / 128, S_LEN / 128, 3), 256, GEMM_SMEM_BYTES>>>(
        q, k, v, wq, bq, wk, bk, wv, bv);

    flash_attn_mma<<<dim3(S_LEN / 64, NHEADS), 128, ATTN_SMEM_BYTES>>>();

    gemm_out<<<dim3(DMODEL / 128, S_LEN / 128), 256, GEMM_SMEM_BYTES>>>(wo, bo, out);
}

// round 6
// speedup vs baseline: 4.0792x; 1.1620x over previous
#include <cuda_runtime.h>
#include <cstdint>
#include <math.h>

#define S_LEN 4096
#define DMODEL 768
#define NHEADS 12
#define DHEAD 64

// Scratch (static device globals — no allocation allowed)
__device__ float g_Qh[NHEADS * S_LEN * DHEAD];   // [h][s][d]  tf32(0.125*qproj)
__device__ float g_Kh[NHEADS * S_LEN * DHEAD];   // [h][s][d]  tf32
__device__ float g_Vt[NHEADS * DHEAD * S_LEN];   // [h][d][s]  tf32, transposed
__device__ float g_Ctx[S_LEN * DMODEL];          // [s][dmodel] tf32
// Pre-rounded (tf32) copies of inputs/weights
__device__ float g_Aq[S_LEN * DMODEL];
__device__ float g_Ak[S_LEN * DMODEL];
__device__ float g_Av[S_LEN * DMODEL];
__device__ float g_Wq[DMODEL * DMODEL];
__device__ float g_Wk[DMODEL * DMODEL];
__device__ float g_Wv[DMODEL * DMODEL];
__device__ float g_Wo[DMODEL * DMODEL];

// ---------------------------------------------------------------------------
// PTX helpers (sm_80-era PTX only — compute_103 baseline-safe)
// ---------------------------------------------------------------------------
__device__ __forceinline__ uint32_t smem_u32(const void* p) {
    uint32_t a;
    asm("{ .reg .u64 t; cvta.to.shared.u64 t, %1; cvt.u32.u64 %0, t; }"
        : "=r"(a) : "l"(p));
    return a;
}

#define CP_ASYNC16(dst, src) \
    asm volatile("cp.async.cg.shared.global [%0], [%1], 16;" \
                 :: "r"(dst), "l"(src))
#define CP_COMMIT() asm volatile("cp.async.commit_group;" ::: "memory")
#define CP_WAIT3()  asm volatile("cp.async.wait_group 3;" ::: "memory")
#define CP_WAIT1()  asm volatile("cp.async.wait_group 1;" ::: "memory")
#define CP_WAIT0()  asm volatile("cp.async.wait_group 0;" ::: "memory")

__device__ __forceinline__ void ldsm_x4(uint32_t* r, uint32_t addr) {
    asm volatile("ldmatrix.sync.aligned.m8n8.x4.shared.b16 {%0,%1,%2,%3}, [%4];"
                 : "=r"(r[0]), "=r"(r[1]), "=r"(r[2]), "=r"(r[3]) : "r"(addr));
}
__device__ __forceinline__ uint32_t tf32r(float f) {
    uint32_t o;
    asm("cvt.rna.tf32.f32 %0, %1;" : "=r"(o) : "f"(f));
    return o;
}
__device__ __forceinline__ float tf32rf(float f) {
    return __uint_as_float(tf32r(f));
}
__device__ __forceinline__ void mma_tf32(float* c, const uint32_t* a, const uint32_t* b) {
    asm volatile(
        "mma.sync.aligned.m16n8k8.row.col.f32.tf32.tf32.f32 "
        "{%0,%1,%2,%3}, {%4,%5,%6,%7}, {%8,%9}, {%0,%1,%2,%3};"
        : "+f"(c[0]), "+f"(c[1]), "+f"(c[2]), "+f"(c[3])
        : "r"(a[0]), "r"(a[1]), "r"(a[2]), "r"(a[3]), "r"(b[0]), "r"(b[1]));
}
__device__ __forceinline__ void sts128u(uint32_t a, uint32_t x, uint32_t y,
                                        uint32_t z, uint32_t w) {
    asm volatile("st.shared.v4.b32 [%0], {%1,%2,%3,%4};"
                 :: "r"(a), "r"(x), "r"(y), "r"(z), "r"(w));
}
__device__ __forceinline__ void sts64u(uint32_t a, uint32_t x, uint32_t y) {
    asm volatile("st.shared.v2.b32 [%0], {%1,%2};" :: "r"(a), "r"(x), "r"(y));
}

// ---------------------------------------------------------------------------
// Pre-round pass: tf32-round inputs and weights (elementwise, memory bound)
// ---------------------------------------------------------------------------
#define NA4 (S_LEN * DMODEL / 4)      // 786432
#define NW4 (DMODEL * DMODEL / 4)     // 147456
#define PRE_TOTAL (3 * NA4 + 4 * NW4) // 2949120

__global__ __launch_bounds__(256)
void round_pre(const float* __restrict__ q, const float* __restrict__ k,
               const float* __restrict__ v,
               const float* __restrict__ wq, const float* __restrict__ wk,
               const float* __restrict__ wv, const float* __restrict__ wo)
{
    int idx = blockIdx.x * 256 + threadIdx.x;
    if (idx >= PRE_TOTAL) return;
    const float4* src;
    float4* dst;
    int local;
    if (idx < 3 * NA4) {
        int t = idx / NA4;
        local = idx - t * NA4;
        src = (const float4*)(t == 0 ? q : t == 1 ? k : v);
        dst = (float4*)(t == 0 ? g_Aq : t == 1 ? g_Ak : g_Av);
    } else {
        int j = idx - 3 * NA4;
        int t = j / NW4;
        local = j - t * NW4;
        src = (const float4*)(t == 0 ? wq : t == 1 ? wk : t == 2 ? wv : wo);
        dst = (float4*)(t == 0 ? g_Wq : t == 1 ? g_Wk : t == 2 ? g_Wv : g_Wo);
    }
    float4 x = src[local];
    float4 y;
    y.x = tf32rf(x.x); y.y = tf32rf(x.y); y.z = tf32rf(x.z); y.w = tf32rf(x.w);
    dst[local] = y;
}

// ---------------------------------------------------------------------------
// TF32 tensor-core GEMM body — operands PRE-ROUNDED, so zero cvts in loop.
// Tile 128x128, BK=16, 256 threads (8 warps 2m x 4n), 4-stage cp.async,
// rows padded to 20 words (bank-conflict-free LDSM). B-frags via paired x4.
// ---------------------------------------------------------------------------
#define ROWW 20
#define HALF_STAGE_BYTES (128 * ROWW * 4)
#define STAGE_BYTES (2 * HALF_STAGE_BYTES)
#define NSTAGE 4
#define GEMM_SMEM_BYTES (NSTAGE * STAGE_BYTES)
#define KT_TILES 48

struct GemmFrag {
    float acc[4][4][4];
};

__device__ __forceinline__ void gemm_core(const float* __restrict__ A,
                                          const float* __restrict__ W,
                                          int m0, int n0, GemmFrag& F)
{
    extern __shared__ float sm[];
    const uint32_t sbase = smem_u32(sm);
    const int tid  = threadIdx.x;
    const int lane = tid & 31;
    const int wid  = tid >> 5;
    const int warp_m = (wid & 1) * 64;
    const int warp_n = (wid >> 1) * 32;

    const char* gA = (const char*)(A + (size_t)m0 * DMODEL);
    const char* gB = (const char*)(W + (size_t)n0 * DMODEL);

    auto issue = [&](int kt) {
        int stage = kt & (NSTAGE - 1);
        uint32_t dstBase = sbase + stage * STAGE_BYTES;
#pragma unroll
        for (int c = 0; c < 4; c++) {
            int idx = tid + c * 256;
            int mat = idx >> 9;
            int i   = idx & 511;
            int row = i >> 2;
            int ch  = i & 3;
            uint32_t dst = dstBase + mat * HALF_STAGE_BYTES + row * (ROWW * 4) + ch * 16;
            const char* src = (mat ? gB : gA) + (size_t)row * 3072 + (size_t)kt * 64 + ch * 16;
            CP_ASYNC16(dst, src);
        }
    };

#pragma unroll
    for (int i = 0; i < 4; i++)
#pragma unroll
        for (int j = 0; j < 4; j++)
#pragma unroll
            for (int r = 0; r < 4; r++) F.acc[i][j][r] = 0.f;

    issue(0); CP_COMMIT();
    issue(1); CP_COMMIT();
    issue(2); CP_COMMIT();

    const int a_rowoff = ((lane >> 3) & 1) * 8 + (lane & 7);
    const int a_half   = (lane >> 4) & 1;
    const int b_row    = lane & 7;
    const int b_half   = (lane >> 3) & 1;
    const int b_pair   = (lane >> 4) & 1;   // selects bn within a pair

    for (int kt = 0; kt < KT_TILES; kt++) {
        if (kt + 3 < KT_TILES) issue(kt + 3);
        CP_COMMIT();
        CP_WAIT3();
        __syncthreads();

        uint32_t aS = sbase + (kt & (NSTAGE - 1)) * STAGE_BYTES;
        uint32_t bS = aS + HALF_STAGE_BYTES;

#pragma unroll
        for (int ks = 0; ks < 2; ks++) {
            uint32_t a[4][4], b[4][2];
#pragma unroll
            for (int am = 0; am < 4; am++) {
                uint32_t addr = aS + (warp_m + am * 16 + a_rowoff) * (ROWW * 4)
                              + ks * 32 + a_half * 16;
                ldsm_x4(a[am], addr);
            }
#pragma unroll
            for (int bp = 0; bp < 2; bp++) {
                uint32_t t4[4];
                uint32_t addr = bS + (warp_n + (bp * 2 + b_pair) * 8 + b_row) * (ROWW * 4)
                              + ks * 32 + b_half * 16;
                ldsm_x4(t4, addr);
                b[bp * 2 + 0][0] = t4[0]; b[bp * 2 + 0][1] = t4[1];
                b[bp * 2 + 1][0] = t4[2]; b[bp * 2 + 1][1] = t4[3];
            }
#pragma unroll
            for (int am = 0; am < 4; am++)
#pragma unroll
                for (int bn = 0; bn < 4; bn++)
                    mma_tf32(F.acc[am][bn], a[am], b[bn]);
        }
        __syncthreads();
    }
}

// Fused Q/K/V projections over pre-rounded operands. blockIdx.z selects proj.
// z=0: Q -> g_Qh = tf32((acc+b)*0.125). z=1: K -> g_Kh tf32. z=2: V -> g_Vt.
__global__ __launch_bounds__(256)
void gemm_qkv(const float* __restrict__ bq, const float* __restrict__ bk,
              const float* __restrict__ bv)
{
    const int z = blockIdx.z;
    const float* A    = (z == 0) ? g_Aq : (z == 1) ? g_Ak : g_Av;
    const float* W    = (z == 0) ? g_Wq : (z == 1) ? g_Wk : g_Wv;
    const float* bias = (z == 0) ? bq : (z == 1) ? bk : bv;

    const int m0 = blockIdx.y * 128;
    const int n0 = blockIdx.x * 128;

    GemmFrag F;
    gemm_core(A, W, m0, n0, F);

    const int lane = threadIdx.x & 31;
    const int wid  = threadIdx.x >> 5;
    const int warp_m = (wid & 1) * 64;
    const int warp_n = (wid >> 1) * 32;
    const int g   = lane >> 2;
    const int tig = lane & 3;

#pragma unroll
    for (int am = 0; am < 4; am++) {
#pragma unroll
        for (int bn = 0; bn < 4; bn++) {
            int ncol = n0 + warp_n + bn * 8 + tig * 2;
            float2 bz = *(const float2*)(bias + ncol);
            int hd = ncol >> 6;
            int d  = ncol & 63;
#pragma unroll
            for (int h = 0; h < 2; h++) {
                int m = m0 + warp_m + am * 16 + g + h * 8;
                float ox = F.acc[am][bn][h * 2 + 0] + bz.x;
                float oy = F.acc[am][bn][h * 2 + 1] + bz.y;
                if (z == 0) {
                    float2 o = make_float2(tf32rf(ox * 0.125f), tf32rf(oy * 0.125f));
                    *(float2*)(g_Qh + ((size_t)hd * S_LEN + m) * DHEAD + d) = o;
                } else if (z == 1) {
                    float2 o = make_float2(tf32rf(ox), tf32rf(oy));
                    *(float2*)(g_Kh + ((size_t)hd * S_LEN + m) * DHEAD + d) = o;
                } else {
                    g_Vt[((size_t)hd * DHEAD + d)     * S_LEN + m] = tf32rf(ox);
                    g_Vt[((size_t)hd * DHEAD + d + 1) * S_LEN + m] = tf32rf(oy);
                }
            }
        }
    }
}

// Output projection: g_Ctx (tf32) @ g_Wo^T + bo -> out (fp32)
__global__ __launch_bounds__(256)
void gemm_out(const float* __restrict__ bo, float* __restrict__ Out)
{
    const int m0 = blockIdx.y * 128;
    const int n0 = blockIdx.x * 128;

    GemmFrag F;
    gemm_core((const float*)g_Ctx, (const float*)g_Wo, m0, n0, F);

    const int lane = threadIdx.x & 31;
    const int wid  = threadIdx.x >> 5;
    const int warp_m = (wid & 1) * 64;
    const int warp_n = (wid >> 1) * 32;
    const int g   = lane >> 2;
    const int tig = lane & 3;

#pragma unroll
    for (int am = 0; am < 4; am++) {
#pragma unroll
        for (int bn = 0; bn < 4; bn++) {
            int ncol = n0 + warp_n + bn * 8 + tig * 2;
            float2 bz = *(const float2*)(bo + ncol);
#pragma unroll
            for (int h = 0; h < 2; h++) {
                int m = m0 + warp_m + am * 16 + g + h * 8;
                float2 o;
                o.x = F.acc[am][bn][h * 2 + 0] + bz.x;
                o.y = F.acc[am][bn][h * 2 + 1] + bz.y;
                *(float2*)(Out + (size_t)m * DMODEL + ncol) = o;
            }
        }
    }
}

// ---------------------------------------------------------------------------
// Tensor-core flash attention (causal), 1-term tf32 QK (both operands
// pre-rounded at producers; scale folded into Q). BM=64 q rows/CTA, BN=64,
// 128 threads (4 warps). V pre-transposed -> paired ldsm_x4 B-frags.
// ---------------------------------------------------------------------------
#define KS_ROWB 272
#define VT_ROWB 272
#define PS_ROWB 272
#define KS_STG  (64 * KS_ROWB)
#define VT_STG  (64 * VT_ROWB)
#define OFF_KS0 0
#define OFF_KS1 (OFF_KS0 + KS_STG)
#define OFF_VT0 (OFF_KS1 + KS_STG)
#define OFF_VT1 (OFF_VT0 + VT_STG)
#define OFF_PS  (OFF_VT1 + VT_STG)
#define ATTN_SMEM_BYTES (OFF_PS + 64 * PS_ROWB)    // 87040

__global__ __launch_bounds__(128)
void flash_attn_mma()
{
    extern __shared__ char smc[];
    const uint32_t sb = smem_u32(smc);
    const int tid  = threadIdx.x;
    const int lane = tid & 31;
    const int w    = tid >> 5;
    const int head = blockIdx.y;
    const int qb   = gridDim.x - 1 - blockIdx.x;   // biggest workload first
    const int q0   = qb * 64;

    const float* Qg = g_Qh + (size_t)head * S_LEN * DHEAD;
    const float* Kg = g_Kh + (size_t)head * S_LEN * DHEAD;
    const float* Vt = g_Vt + (size_t)head * DHEAD * S_LEN;

    // ---- Q prologue: stage rows to smem, load fragments (already scaled) ----
#pragma unroll
    for (int p = 0; p < 8; p++) {
        int e   = tid + p * 128;
        int row = e >> 4;
        int c4  = e & 15;
        float4 v = *(const float4*)(Qg + (size_t)(q0 + row) * DHEAD + c4 * 4);
        sts128u(sb + OFF_PS + row * PS_ROWB + c4 * 16,
                __float_as_uint(v.x), __float_as_uint(v.y),
                __float_as_uint(v.z), __float_as_uint(v.w));
    }
    __syncthreads();

    const int a_rowoff = ((lane >> 3) & 1) * 8 + (lane & 7);
    const int a_half   = (lane >> 4) & 1;
    const uint32_t aAddrBase = sb + OFF_PS + (w * 16 + a_rowoff) * PS_ROWB + a_half * 16;

    uint32_t qh[8][4];
#pragma unroll
    for (int kb = 0; kb < 8; kb++)
        ldsm_x4(qh[kb], aAddrBase + kb * 32);
    // Ps rows 16w..16w+15 warp-private from here (P staging).

    float m_[2] = {-1e30f, -1e30f};
    float l_[2] = {0.f, 0.f};
    float o[8][4];
#pragma unroll
    for (int nb = 0; nb < 8; nb++)
#pragma unroll
        for (int j = 0; j < 4; j++) o[nb][j] = 0.f;

    auto issue = [&](int t) {
        uint32_t ksB = sb + ((t & 1) ? OFF_KS1 : OFF_KS0);
        uint32_t vtB = sb + ((t & 1) ? OFF_VT1 : OFF_VT0);
        int kv0 = t * 64;
#pragma unroll
        for (int c = 0; c < 16; c++) {
            int i   = tid + c * 128;
            int mat = i >> 10;
            int j   = i & 1023;
            int row = j >> 4;
            int ch  = j & 15;
            if (mat == 0) {
                CP_ASYNC16(ksB + row * KS_ROWB + ch * 16,
                           (const char*)(Kg + (size_t)(kv0 + row) * DHEAD) + ch * 16);
            } else {
                CP_ASYNC16(vtB + row * VT_ROWB + ch * 16,
                           (const char*)(Vt + (size_t)row * S_LEN + kv0) + ch * 16);
            }
        }
    };

    issue(0); CP_COMMIT();

    const int b_nboff = ((lane >> 4) & 1) * 8;
    const int b_row   = lane & 7;
    const int b_half  = (lane >> 3) & 1;
    const int v_pair  = (lane >> 4) & 1;
    const int g       = lane >> 2;
    const int tg      = lane & 3;
    const int ntiles  = qb + 1;

    for (int t = 0; t < ntiles; t++) {
        if (t + 1 < ntiles) { issue(t + 1); CP_COMMIT(); CP_WAIT1(); }
        else                { CP_WAIT0(); }
        __syncthreads();

        uint32_t ksS = sb + ((t & 1) ? OFF_KS1 : OFF_KS0);
        uint32_t vtS = sb + ((t & 1) ? OFF_VT1 : OFF_VT0);

        // ---- S = Q K^T (1-term, both pre-rounded, scale folded into Q) ----
        float s[8][4];
#pragma unroll
        for (int nb = 0; nb < 8; nb++)
#pragma unroll
            for (int j = 0; j < 4; j++) s[nb][j] = 0.f;

#pragma unroll
        for (int kb = 0; kb < 8; kb++) {
            uint32_t bh[16];
#pragma unroll
            for (int bp = 0; bp < 4; bp++) {
                uint32_t roff = (bp * 16 + b_nboff + b_row) * KS_ROWB + kb * 32 + b_half * 16;
                ldsm_x4(&bh[bp * 4], ksS + roff);
            }
#pragma unroll
            for (int nb = 0; nb < 8; nb++)
                mma_tf32(s[nb], qh[kb], &bh[nb * 2]);
        }

        // ---- causal mask (diagonal tile only) ----
        if (t == qb) {
            int kv0 = t * 64;
            int qa = q0 + w * 16 + g;
#pragma unroll
            for (int nb = 0; nb < 8; nb++) {
#pragma unroll
                for (int j = 0; j < 4; j++) {
                    int col = kv0 + nb * 8 + 2 * tg + (j & 1);
                    int row = qa + (j >> 1) * 8;
                    if (col > row) s[nb][j] = -1e30f;
                }
            }
        }

        // ---- online softmax on fragments (rows g and g+8) ----
#pragma unroll
        for (int r = 0; r < 2; r++) {
            float mx = m_[r];
#pragma unroll
            for (int nb = 0; nb < 8; nb++)
                mx = fmaxf(mx, fmaxf(s[nb][2 * r], s[nb][2 * r + 1]));
            mx = fmaxf(mx, __shfl_xor_sync(0xffffffffu, mx, 1));
            mx = fmaxf(mx, __shfl_xor_sync(0xffffffffu, mx, 2));
            float esc = __expf(m_[r] - mx);
            float sum = 0.f;
#pragma unroll
            for (int nb = 0; nb < 8; nb++) {
#pragma unroll
                for (int jj = 0; jj < 2; jj++) {
                    float p = __expf(s[nb][2 * r + jj] - mx);
                    uint32_t pr = tf32r(p);            // round BEFORE summing
                    s[nb][2 * r + jj] = __uint_as_float(pr);
                    sum += __uint_as_float(pr);
                }
            }
            sum += __shfl_xor_sync(0xffffffffu, sum, 1);
            sum += __shfl_xor_sync(0xffffffffu, sum, 2);
            l_[r] = l_[r] * esc + sum;
            m_[r] = mx;
#pragma unroll
            for (int nb = 0; nb < 8; nb++) {
                o[nb][2 * r]     *= esc;
                o[nb][2 * r + 1] *= esc;
            }
        }

        // ---- stage P (tf32 values) in warp-private Ps rows ----
        uint32_t psW = sb + OFF_PS + (w * 16 + g) * PS_ROWB + tg * 8;
#pragma unroll
        for (int nb = 0; nb < 8; nb++) {
            sts64u(psW + nb * 32,
                   __float_as_uint(s[nb][0]), __float_as_uint(s[nb][1]));
            sts64u(psW + 8 * PS_ROWB + nb * 32,
                   __float_as_uint(s[nb][2]), __float_as_uint(s[nb][3]));
        }
        __syncwarp();

        // ---- O += P V  (paired x4 V-fragments: lanes 16-31 fetch kb+1) ----
#pragma unroll
        for (int kp = 0; kp < 4; kp++) {
            uint32_t pa0[4], pa1[4];
            ldsm_x4(pa0, aAddrBase + (2 * kp)     * 32);
            ldsm_x4(pa1, aAddrBase + (2 * kp + 1) * 32);
#pragma unroll
            for (int nb = 0; nb < 8; nb++) {
                uint32_t t4[4];
                ldsm_x4(t4, vtS + (nb * 8 + b_row) * VT_ROWB
                            + (2 * kp + v_pair) * 32 + b_half * 16);
                mma_tf32(o[nb], pa0, t4);
                mma_tf32(o[nb], pa1, t4 + 2);
            }
        }
        __syncthreads();   // buffers free before next overwrite
    }

    // ---- epilogue: normalize, round to tf32, write context [s][dmodel] ----
#pragma unroll
    for (int r = 0; r < 2; r++) {
        float inv = 1.f / l_[r];
        int qrow = q0 + w * 16 + g + r * 8;
        float* dst = g_Ctx + (size_t)qrow * DMODEL + head * DHEAD + 2 * tg;
#pragma unroll
        for (int nb = 0; nb < 8; nb++) {
            float2 ov;
            ov.x = tf32rf(o[nb][2 * r]     * inv);
            ov.y = tf32rf(o[nb][2 * r + 1] * inv);
            *(float2*)(dst + nb * 8) = ov;
        }
    }
}

// ---------------------------------------------------------------------------
extern "C" void kernel_launch(void* const* d_in, const int* in_sizes, int n_in,
                              void* d_out, int out_size)
{
    const float* q  = (const float*)d_in[0];
    const float* k  = (const float*)d_in[1];
    const float* v  = (const float*)d_in[2];
    const float* wq = (const float*)d_in[3];
    const float* bq = (const float*)d_in[4];
    const float* wk = (const float*)d_in[5];
    const float* bk = (const float*)d_in[6];
    const float* wv = (const float*)d_in[7];
    const float* bv = (const float*)d_in[8];
    const float* wo = (const float*)d_in[9];
    const float* bo = (const float*)d_in[10];
    float* out = (float*)d_out;

    cudaFuncSetAttribute(gemm_qkv, cudaFuncAttributeMaxDynamicSharedMemorySize, GEMM_SMEM_BYTES);
    cudaFuncSetAttribute(gemm_out, cudaFuncAttributeMaxDynamicSharedMemorySize, GEMM_SMEM_BYTES);
    cudaFuncSetAttribute(flash_attn_mma, cudaFuncAttributeMaxDynamicSharedMemorySize, ATTN_SMEM_BYTES);

    round_pre<<<(PRE_TOTAL + 255) / 256, 256>>>(q, k, v, wq, wk, wv, wo);

    gemm_qkv<<<dim3(DMODEL / 128, S_LEN / 128, 3), 256, GEMM_SMEM_BYTES>>>(bq, bk, bv);

    flash_attn_mma<<<dim3(S_LEN / 64, NHEADS), 128, ATTN_SMEM_BYTES>>>();

    gemm_out<<<dim3(DMODEL / 128, S_LEN / 128), 256, GEMM_SMEM_BYTES>>>(bo, out);
}

// round 7
// speedup vs baseline: 4.2112x; 1.0324x over previous
#include <cuda_runtime.h>
#include <cstdint>
#include <math.h>

#define S_LEN 4096
#define DMODEL 768
#define NHEADS 12
#define DHEAD 64

// Scratch (static device globals — no allocation allowed)
__device__ float g_Qh[NHEADS * S_LEN * DHEAD];   // [h][s][d]  tf32(0.125*qproj)
__device__ float g_Kh[NHEADS * S_LEN * DHEAD];   // [h][s][d]  tf32
__device__ float g_Vt[NHEADS * DHEAD * S_LEN];   // [h][d][s]  tf32, transposed
__device__ float g_Ctx[S_LEN * DMODEL];          // [s][dmodel] tf32
// Pre-rounded (tf32) copies of inputs/weights
__device__ float g_Aq[S_LEN * DMODEL];
__device__ float g_Ak[S_LEN * DMODEL];
__device__ float g_Av[S_LEN * DMODEL];
__device__ float g_Wq[DMODEL * DMODEL];
__device__ float g_Wk[DMODEL * DMODEL];
__device__ float g_Wv[DMODEL * DMODEL];
__device__ float g_Wo[DMODEL * DMODEL];

// ---------------------------------------------------------------------------
// PTX helpers (sm_80-era PTX only — compute_103 baseline-safe)
// ---------------------------------------------------------------------------
__device__ __forceinline__ uint32_t smem_u32(const void* p) {
    uint32_t a;
    asm("{ .reg .u64 t; cvta.to.shared.u64 t, %1; cvt.u32.u64 %0, t; }"
        : "=r"(a) : "l"(p));
    return a;
}

#define CP_ASYNC16(dst, src) \
    asm volatile("cp.async.cg.shared.global [%0], [%1], 16;" \
                 :: "r"(dst), "l"(src))
#define CP_COMMIT() asm volatile("cp.async.commit_group;" ::: "memory")
#define CP_WAIT2()  asm volatile("cp.async.wait_group 2;" ::: "memory")
#define CP_WAIT0()  asm volatile("cp.async.wait_group 0;" ::: "memory")

__device__ __forceinline__ void ldsm_x4(uint32_t* r, uint32_t addr) {
    asm volatile("ldmatrix.sync.aligned.m8n8.x4.shared.b16 {%0,%1,%2,%3}, [%4];"
                 : "=r"(r[0]), "=r"(r[1]), "=r"(r[2]), "=r"(r[3]) : "r"(addr));
}
__device__ __forceinline__ uint32_t tf32r(float f) {
    uint32_t o;
    asm("cvt.rna.tf32.f32 %0, %1;" : "=r"(o) : "f"(f));
    return o;
}
__device__ __forceinline__ float tf32rf(float f) {
    return __uint_as_float(tf32r(f));
}
__device__ __forceinline__ void mma_tf32(float* c, const uint32_t* a, const uint32_t* b) {
    asm volatile(
        "mma.sync.aligned.m16n8k8.row.col.f32.tf32.tf32.f32 "
        "{%0,%1,%2,%3}, {%4,%5,%6,%7}, {%8,%9}, {%0,%1,%2,%3};"
        : "+f"(c[0]), "+f"(c[1]), "+f"(c[2]), "+f"(c[3])
        : "r"(a[0]), "r"(a[1]), "r"(a[2]), "r"(a[3]), "r"(b[0]), "r"(b[1]));
}
__device__ __forceinline__ void sts128u(uint32_t a, uint32_t x, uint32_t y,
                                        uint32_t z, uint32_t w) {
    asm volatile("st.shared.v4.b32 [%0], {%1,%2,%3,%4};"
                 :: "r"(a), "r"(x), "r"(y), "r"(z), "r"(w));
}
__device__ __forceinline__ void sts64u(uint32_t a, uint32_t x, uint32_t y) {
    asm volatile("st.shared.v2.b32 [%0], {%1,%2};" :: "r"(a), "r"(x), "r"(y));
}

// ---------------------------------------------------------------------------
// Pre-round pass: tf32-round inputs and weights (elementwise, memory bound)
// ---------------------------------------------------------------------------
#define NA4 (S_LEN * DMODEL / 4)
#define NW4 (DMODEL * DMODEL / 4)
#define PRE_TOTAL (3 * NA4 + 4 * NW4)

__global__ __launch_bounds__(256)
void round_pre(const float* __restrict__ q, const float* __restrict__ k,
               const float* __restrict__ v,
               const float* __restrict__ wq, const float* __restrict__ wk,
               const float* __restrict__ wv, const float* __restrict__ wo)
{
    int idx = blockIdx.x * 256 + threadIdx.x;
    if (idx >= PRE_TOTAL) return;
    const float4* src;
    float4* dst;
    int local;
    if (idx < 3 * NA4) {
        int t = idx / NA4;
        local = idx - t * NA4;
        src = (const float4*)(t == 0 ? q : t == 1 ? k : v);
        dst = (float4*)(t == 0 ? g_Aq : t == 1 ? g_Ak : g_Av);
    } else {
        int j = idx - 3 * NA4;
        int t = j / NW4;
        local = j - t * NW4;
        src = (const float4*)(t == 0 ? wq : t == 1 ? wk : t == 2 ? wv : wo);
        dst = (float4*)(t == 0 ? g_Wq : t == 1 ? g_Wk : t == 2 ? g_Wv : g_Wo);
    }
    float4 x = src[local];
    float4 y;
    y.x = tf32rf(x.x); y.y = tf32rf(x.y); y.z = tf32rf(x.z); y.w = tf32rf(x.w);
    dst[local] = y;
}

// ---------------------------------------------------------------------------
// TF32 GEMM core, 128x128 tile, BK=16, single barrier per k-tile.
// ---------------------------------------------------------------------------
#define ROWW 20
#define HALF_STAGE_BYTES (128 * ROWW * 4)
#define STAGE_BYTES (2 * HALF_STAGE_BYTES)
#define NSTAGE 4
#define GEMM_SMEM_BYTES (NSTAGE * STAGE_BYTES)
#define KT_TILES 48

struct GemmFrag {
    float acc[4][4][4];
};

__device__ __forceinline__ void gemm_core(const float* __restrict__ A,
                                          const float* __restrict__ W,
                                          int m0, int n0, GemmFrag& F)
{
    extern __shared__ float sm[];
    const uint32_t sbase = smem_u32(sm);
    const int tid  = threadIdx.x;
    const int lane = tid & 31;
    const int wid  = tid >> 5;
    const int warp_m = (wid & 1) * 64;
    const int warp_n = (wid >> 1) * 32;

    const char* gA = (const char*)(A + (size_t)m0 * DMODEL);
    const char* gB = (const char*)(W + (size_t)n0 * DMODEL);

    auto issue = [&](int kt) {
        int stage = kt & (NSTAGE - 1);
        uint32_t dstBase = sbase + stage * STAGE_BYTES;
#pragma unroll
        for (int c = 0; c < 4; c++) {
            int idx = tid + c * 256;
            int mat = idx >> 9;
            int i   = idx & 511;
            int row = i >> 2;
            int ch  = i & 3;
            uint32_t dst = dstBase + mat * HALF_STAGE_BYTES + row * (ROWW * 4) + ch * 16;
            const char* src = (mat ? gB : gA) + (size_t)row * 3072 + (size_t)kt * 64 + ch * 16;
            CP_ASYNC16(dst, src);
        }
    };

#pragma unroll
    for (int i = 0; i < 4; i++)
#pragma unroll
        for (int j = 0; j < 4; j++)
#pragma unroll
            for (int r = 0; r < 4; r++) F.acc[i][j][r] = 0.f;

    issue(0); CP_COMMIT();
    issue(1); CP_COMMIT();
    issue(2); CP_COMMIT();

    const int a_rowoff = ((lane >> 3) & 1) * 8 + (lane & 7);
    const int a_half   = (lane >> 4) & 1;
    const int b_row    = lane & 7;
    const int b_half   = (lane >> 3) & 1;
    const int b_pair   = (lane >> 4) & 1;

    for (int kt = 0; kt < KT_TILES; kt++) {
        CP_WAIT2();
        __syncthreads();
        if (kt + 3 < KT_TILES) issue(kt + 3);
        CP_COMMIT();

        uint32_t aS = sbase + (kt & (NSTAGE - 1)) * STAGE_BYTES;
        uint32_t bS = aS + HALF_STAGE_BYTES;

#pragma unroll
        for (int ks = 0; ks < 2; ks++) {
            uint32_t a[4][4], b[4][2];
#pragma unroll
            for (int am = 0; am < 4; am++) {
                uint32_t addr = aS + (warp_m + am * 16 + a_rowoff) * (ROWW * 4)
                              + ks * 32 + a_half * 16;
                ldsm_x4(a[am], addr);
            }
#pragma unroll
            for (int bp = 0; bp < 2; bp++) {
                uint32_t t4[4];
                uint32_t addr = bS + (warp_n + (bp * 2 + b_pair) * 8 + b_row) * (ROWW * 4)
                              + ks * 32 + b_half * 16;
                ldsm_x4(t4, addr);
                b[bp * 2 + 0][0] = t4[0]; b[bp * 2 + 0][1] = t4[1];
                b[bp * 2 + 1][0] = t4[2]; b[bp * 2 + 1][1] = t4[3];
            }
#pragma unroll
            for (int am = 0; am < 4; am++)
#pragma unroll
                for (int bn = 0; bn < 4; bn++)
                    mma_tf32(F.acc[am][bn], a[am], b[bn]);
        }
    }
}

// Fused Q/K/V projections over pre-rounded operands.
__global__ __launch_bounds__(256)
void gemm_qkv(const float* __restrict__ bq, const float* __restrict__ bk,
              const float* __restrict__ bv)
{
    const int z = blockIdx.z;
    const float* A    = (z == 0) ? g_Aq : (z == 1) ? g_Ak : g_Av;
    const float* W    = (z == 0) ? g_Wq : (z == 1) ? g_Wk : g_Wv;
    const float* bias = (z == 0) ? bq : (z == 1) ? bk : bv;

    const int m0 = blockIdx.y * 128;
    const int n0 = blockIdx.x * 128;

    GemmFrag F;
    gemm_core(A, W, m0, n0, F);

    const int lane = threadIdx.x & 31;
    const int wid  = threadIdx.x >> 5;
    const int warp_m = (wid & 1) * 64;
    const int warp_n = (wid >> 1) * 32;
    const int g   = lane >> 2;
    const int tig = lane & 3;

#pragma unroll
    for (int am = 0; am < 4; am++) {
#pragma unroll
        for (int bn = 0; bn < 4; bn++) {
            int ncol = n0 + warp_n + bn * 8 + tig * 2;
            float2 bz = *(const float2*)(bias + ncol);
            int hd = ncol >> 6;
            int d  = ncol & 63;
#pragma unroll
            for (int h = 0; h < 2; h++) {
                int m = m0 + warp_m + am * 16 + g + h * 8;
                float ox = F.acc[am][bn][h * 2 + 0] + bz.x;
                float oy = F.acc[am][bn][h * 2 + 1] + bz.y;
                if (z == 0) {
                    float2 o = make_float2(tf32rf(ox * 0.125f), tf32rf(oy * 0.125f));
                    *(float2*)(g_Qh + ((size_t)hd * S_LEN + m) * DHEAD + d) = o;
                } else if (z == 1) {
                    float2 o = make_float2(tf32rf(ox), tf32rf(oy));
                    *(float2*)(g_Kh + ((size_t)hd * S_LEN + m) * DHEAD + d) = o;
                } else {
                    g_Vt[((size_t)hd * DHEAD + d)     * S_LEN + m] = tf32rf(ox);
                    g_Vt[((size_t)hd * DHEAD + d + 1) * S_LEN + m] = tf32rf(oy);
                }
            }
        }
    }
}

// ---------------------------------------------------------------------------
// Output projection, 64x128 tile (384 CTAs), single barrier per k-tile.
// ---------------------------------------------------------------------------
#define O_A_BYTES (64 * ROWW * 4)            // 5120
#define O_STAGE_BYTES (O_A_BYTES + HALF_STAGE_BYTES)   // 15360
#define O_SMEM_BYTES (NSTAGE * O_STAGE_BYTES)          // 61440

__global__ __launch_bounds__(256)
void gemm_out(const float* __restrict__ bo, float* __restrict__ Out)
{
    extern __shared__ float sm[];
    const uint32_t sbase = smem_u32(sm);
    const int tid  = threadIdx.x;
    const int lane = tid & 31;
    const int wid  = tid >> 5;
    const int m0 = blockIdx.y * 64;
    const int n0 = blockIdx.x * 128;
    const int warp_n = wid * 16;

    const char* gA = (const char*)((const float*)g_Ctx + (size_t)m0 * DMODEL);
    const char* gB = (const char*)((const float*)g_Wo + (size_t)n0 * DMODEL);

    auto issue = [&](int kt) {
        int stage = kt & (NSTAGE - 1);
        uint32_t dstBase = sbase + stage * O_STAGE_BYTES;
#pragma unroll
        for (int c = 0; c < 3; c++) {
            int idx = tid + c * 256;            // 0..767
            if (idx < 256) {                    // A: 64 rows x 4 chunks
                int row = idx >> 2;
                int ch  = idx & 3;
                CP_ASYNC16(dstBase + row * (ROWW * 4) + ch * 16,
                           gA + (size_t)row * 3072 + (size_t)kt * 64 + ch * 16);
            } else {                            // B: 128 rows x 4 chunks
                int j = idx - 256;
                int row = j >> 2;
                int ch  = j & 3;
                CP_ASYNC16(dstBase + O_A_BYTES + row * (ROWW * 4) + ch * 16,
                           gB + (size_t)row * 3072 + (size_t)kt * 64 + ch * 16);
            }
        }
    };

    float acc[4][2][4];
#pragma unroll
    for (int i = 0; i < 4; i++)
#pragma unroll
        for (int j = 0; j < 2; j++)
#pragma unroll
            for (int r = 0; r < 4; r++) acc[i][j][r] = 0.f;

    issue(0); CP_COMMIT();
    issue(1); CP_COMMIT();
    issue(2); CP_COMMIT();

    const int a_rowoff = ((lane >> 3) & 1) * 8 + (lane & 7);
    const int a_half   = (lane >> 4) & 1;
    const int b_row    = lane & 7;
    const int b_half   = (lane >> 3) & 1;
    const int b_pair   = (lane >> 4) & 1;

    for (int kt = 0; kt < KT_TILES; kt++) {
        CP_WAIT2();
        __syncthreads();
        if (kt + 3 < KT_TILES) issue(kt + 3);
        CP_COMMIT();

        uint32_t aS = sbase + (kt & (NSTAGE - 1)) * O_STAGE_BYTES;
        uint32_t bS = aS + O_A_BYTES;

#pragma unroll
        for (int ks = 0; ks < 2; ks++) {
            uint32_t a[4][4], b[2][2];
#pragma unroll
            for (int am = 0; am < 4; am++) {
                uint32_t addr = aS + (am * 16 + a_rowoff) * (ROWW * 4)
                              + ks * 32 + a_half * 16;
                ldsm_x4(a[am], addr);
            }
            {
                uint32_t t4[4];
                uint32_t addr = bS + (warp_n + b_pair * 8 + b_row) * (ROWW * 4)
                              + ks * 32 + b_half * 16;
                ldsm_x4(t4, addr);
                b[0][0] = t4[0]; b[0][1] = t4[1];
                b[1][0] = t4[2]; b[1][1] = t4[3];
            }
#pragma unroll
            for (int am = 0; am < 4; am++)
#pragma unroll
                for (int bn = 0; bn < 2; bn++)
                    mma_tf32(acc[am][bn], a[am], b[bn]);
        }
    }

    const int g   = lane >> 2;
    const int tig = lane & 3;
#pragma unroll
    for (int am = 0; am < 4; am++) {
#pragma unroll
        for (int bn = 0; bn < 2; bn++) {
            int ncol = n0 + warp_n + bn * 8 + tig * 2;
            float2 bz = *(const float2*)(bo + ncol);
#pragma unroll
            for (int h = 0; h < 2; h++) {
                int m = m0 + am * 16 + g + h * 8;
                float2 o;
                o.x = acc[am][bn][h * 2 + 0] + bz.x;
                o.y = acc[am][bn][h * 2 + 1] + bz.y;
                *(float2*)(Out + (size_t)m * DMODEL + ncol) = o;
            }
        }
    }
}

// ---------------------------------------------------------------------------
// Tensor-core flash attention (causal), software-pipelined:
// iteration t does softmax(S_t) + O += P_t V_t interleaved with S_{t+1}=Q K_{t+1}.
// BM=64, BN=64, 128 threads (4 warps). 1 barrier per tile.
// ---------------------------------------------------------------------------
#define KS_ROWB 272
#define VT_ROWB 272
#define PS_ROWB 272
#define KS_STG  (64 * KS_ROWB)
#define VT_STG  (64 * VT_ROWB)
#define OFF_KS0 0
#define OFF_KS1 (OFF_KS0 + KS_STG)
#define OFF_VT0 (OFF_KS1 + KS_STG)
#define OFF_VT1 (OFF_VT0 + VT_STG)
#define OFF_PS  (OFF_VT1 + VT_STG)
#define ATTN_SMEM_BYTES (OFF_PS + 64 * PS_ROWB)    // 87040

__global__ __launch_bounds__(128)
void flash_attn_mma()
{
    extern __shared__ char smc[];
    const uint32_t sb = smem_u32(smc);
    const int tid  = threadIdx.x;
    const int lane = tid & 31;
    const int w    = tid >> 5;
    const int head = blockIdx.y;
    const int qb   = gridDim.x - 1 - blockIdx.x;   // biggest workload first
    const int q0   = qb * 64;

    const float* Qg = g_Qh + (size_t)head * S_LEN * DHEAD;
    const float* Kg = g_Kh + (size_t)head * S_LEN * DHEAD;
    const float* Vt = g_Vt + (size_t)head * DHEAD * S_LEN;

    // ---- Q prologue: stage rows to smem, load fragments (already scaled) ----
#pragma unroll
    for (int p = 0; p < 8; p++) {
        int e   = tid + p * 128;
        int row = e >> 4;
        int c4  = e & 15;
        float4 v = *(const float4*)(Qg + (size_t)(q0 + row) * DHEAD + c4 * 4);
        sts128u(sb + OFF_PS + row * PS_ROWB + c4 * 16,
                __float_as_uint(v.x), __float_as_uint(v.y),
                __float_as_uint(v.z), __float_as_uint(v.w));
    }
    __syncthreads();

    const int a_rowoff = ((lane >> 3) & 1) * 8 + (lane & 7);
    const int a_half   = (lane >> 4) & 1;
    const uint32_t aAddrBase = sb + OFF_PS + (w * 16 + a_rowoff) * PS_ROWB + a_half * 16;

    uint32_t qh[8][4];
#pragma unroll
    for (int kb = 0; kb < 8; kb++)
        ldsm_x4(qh[kb], aAddrBase + kb * 32);
    __syncthreads();   // all Q fragments read before PS reused for P staging

    float m_[2] = {-1e30f, -1e30f};
    float l_[2] = {0.f, 0.f};
    float o[8][4];
#pragma unroll
    for (int nb = 0; nb < 8; nb++)
#pragma unroll
        for (int j = 0; j < 4; j++) o[nb][j] = 0.f;

    auto issue_K = [&](int t) {
        uint32_t ksB = sb + ((t & 1) ? OFF_KS1 : OFF_KS0);
        int kv0 = t * 64;
#pragma unroll
        for (int c = 0; c < 8; c++) {
            int j = tid + c * 128;
            int row = j >> 4;
            int ch  = j & 15;
            CP_ASYNC16(ksB + row * KS_ROWB + ch * 16,
                       (const char*)(Kg + (size_t)(kv0 + row) * DHEAD) + ch * 16);
        }
    };
    auto issue_V = [&](int t) {
        uint32_t vtB = sb + ((t & 1) ? OFF_VT1 : OFF_VT0);
        int kv0 = t * 64;
#pragma unroll
        for (int c = 0; c < 8; c++) {
            int j = tid + c * 128;
            int row = j >> 4;
            int ch  = j & 15;
            CP_ASYNC16(vtB + row * VT_ROWB + ch * 16,
                       (const char*)(Vt + (size_t)row * S_LEN + kv0) + ch * 16);
        }
    };

    const int ntiles = qb + 1;
    issue_K(0); CP_COMMIT();
    if (ntiles > 1) issue_K(1);
    CP_COMMIT();
    issue_V(0); CP_COMMIT();
    CP_WAIT2();          // K_0 complete; K_1, V_0 in flight
    __syncthreads();

    const int b_nboff = ((lane >> 4) & 1) * 8;
    const int b_row   = lane & 7;
    const int b_half  = (lane >> 3) & 1;
    const int v_pair  = (lane >> 4) & 1;
    const int g       = lane >> 2;
    const int tg      = lane & 3;

    // ---- prologue compute: S_0 = Q K_0 ----
    float s[8][4];
#pragma unroll
    for (int nb = 0; nb < 8; nb++)
#pragma unroll
        for (int j = 0; j < 4; j++) s[nb][j] = 0.f;
    {
        uint32_t ksS = sb + OFF_KS0;
#pragma unroll
        for (int kb = 0; kb < 8; kb++) {
            uint32_t bh[16];
#pragma unroll
            for (int bp = 0; bp < 4; bp++) {
                uint32_t roff = (bp * 16 + b_nboff + b_row) * KS_ROWB + kb * 32 + b_half * 16;
                ldsm_x4(&bh[bp * 4], ksS + roff);
            }
#pragma unroll
            for (int nb = 0; nb < 8; nb++)
                mma_tf32(s[nb], qh[kb], &bh[nb * 2]);
        }
    }

    for (int t = 0; t < ntiles; t++) {
        CP_WAIT0();          // everything issued so far complete (K_{t+1}, V_t)
        __syncthreads();     // publish copies; all warps done with prev compute
        if (t + 2 < ntiles) issue_K(t + 2);
        CP_COMMIT();
        if (t + 1 < ntiles) issue_V(t + 1);
        CP_COMMIT();

        const bool do_qk = (t + 1 < ntiles);
        uint32_t ksN = sb + (((t + 1) & 1) ? OFF_KS1 : OFF_KS0);
        uint32_t vtS = sb + ((t & 1) ? OFF_VT1 : OFF_VT0);

        // ---- causal mask on S_t (diagonal tile only) ----
        if (t == qb) {
            int kv0 = t * 64;
            int qa = q0 + w * 16 + g;
#pragma unroll
            for (int nb = 0; nb < 8; nb++) {
#pragma unroll
                for (int j = 0; j < 4; j++) {
                    int col = kv0 + nb * 8 + 2 * tg + (j & 1);
                    int row = qa + (j >> 1) * 8;
                    if (col > row) s[nb][j] = -1e30f;
                }
            }
        }

        // ---- online softmax on S_t fragments (rows g and g+8) ----
#pragma unroll
        for (int r = 0; r < 2; r++) {
            float mx = m_[r];
#pragma unroll
            for (int nb = 0; nb < 8; nb++)
                mx = fmaxf(mx, fmaxf(s[nb][2 * r], s[nb][2 * r + 1]));
            mx = fmaxf(mx, __shfl_xor_sync(0xffffffffu, mx, 1));
            mx = fmaxf(mx, __shfl_xor_sync(0xffffffffu, mx, 2));
            float esc = __expf(m_[r] - mx);
            float sum = 0.f;
#pragma unroll
            for (int nb = 0; nb < 8; nb++) {
#pragma unroll
                for (int jj = 0; jj < 2; jj++) {
                    float p = __expf(s[nb][2 * r + jj] - mx);
                    uint32_t pr = tf32r(p);
                    s[nb][2 * r + jj] = __uint_as_float(pr);
                    sum += __uint_as_float(pr);
                }
            }
            sum += __shfl_xor_sync(0xffffffffu, sum, 1);
            sum += __shfl_xor_sync(0xffffffffu, sum, 2);
            l_[r] = l_[r] * esc + sum;
            m_[r] = mx;
#pragma unroll
            for (int nb = 0; nb < 8; nb++) {
                o[nb][2 * r]     *= esc;
                o[nb][2 * r + 1] *= esc;
            }
        }

        // ---- stage P_t in warp-private Ps rows ----
        uint32_t psW = sb + OFF_PS + (w * 16 + g) * PS_ROWB + tg * 8;
#pragma unroll
        for (int nb = 0; nb < 8; nb++) {
            sts64u(psW + nb * 32,
                   __float_as_uint(s[nb][0]), __float_as_uint(s[nb][1]));
            sts64u(psW + 8 * PS_ROWB + nb * 32,
                   __float_as_uint(s[nb][2]), __float_as_uint(s[nb][3]));
        }
        __syncwarp();

        // zero s for S_{t+1}
        if (do_qk) {
#pragma unroll
            for (int nb = 0; nb < 8; nb++)
#pragma unroll
                for (int j = 0; j < 4; j++) s[nb][j] = 0.f;
        }

        // ---- interleaved: S_{t+1} = Q K_{t+1}  +  O += P_t V_t ----
#pragma unroll
        for (int u = 0; u < 4; u++) {
            if (do_qk) {
#pragma unroll
                for (int kk = 0; kk < 2; kk++) {
                    int kb = 2 * u + kk;
                    uint32_t bh[16];
#pragma unroll
                    for (int bp = 0; bp < 4; bp++) {
                        uint32_t roff = (bp * 16 + b_nboff + b_row) * KS_ROWB
                                      + kb * 32 + b_half * 16;
                        ldsm_x4(&bh[bp * 4], ksN + roff);
                    }
#pragma unroll
                    for (int nb = 0; nb < 8; nb++)
                        mma_tf32(s[nb], qh[kb], &bh[nb * 2]);
                }
            }
            {
                uint32_t pa0[4], pa1[4];
                ldsm_x4(pa0, aAddrBase + (2 * u)     * 32);
                ldsm_x4(pa1, aAddrBase + (2 * u + 1) * 32);
#pragma unroll
                for (int nb = 0; nb < 8; nb++) {
                    uint32_t t4[4];
                    ldsm_x4(t4, vtS + (nb * 8 + b_row) * VT_ROWB
                                + (2 * u + v_pair) * 32 + b_half * 16);
                    mma_tf32(o[nb], pa0, t4);
                    mma_tf32(o[nb], pa1, t4 + 2);
                }
            }
        }
    }

    // ---- epilogue: normalize, round to tf32, write context [s][dmodel] ----
#pragma unroll
    for (int r = 0; r < 2; r++) {
        float inv = 1.f / l_[r];
        int qrow = q0 + w * 16 + g + r * 8;
        float* dst = g_Ctx + (size_t)qrow * DMODEL + head * DHEAD + 2 * tg;
#pragma unroll
        for (int nb = 0; nb < 8; nb++) {
            float2 ov;
            ov.x = tf32rf(o[nb][2 * r]     * inv);
            ov.y = tf32rf(o[nb][2 * r + 1] * inv);
            *(float2*)(dst + nb * 8) = ov;
        }
    }
}

// ---------------------------------------------------------------------------
extern "C" void kernel_launch(void* const* d_in, const int* in_sizes, int n_in,
                              void* d_out, int out_size)
{
    const float* q  = (const float*)d_in[0];
    const float* k  = (const float*)d_in[1];
    const float* v  = (const float*)d_in[2];
    const float* wq = (const float*)d_in[3];
    const float* bq = (const float*)d_in[4];
    const float* wk = (const float*)d_in[5];
    const float* bk = (const float*)d_in[6];
    const float* wv = (const float*)d_in[7];
    const float* bv = (const float*)d_in[8];
    const float* wo = (const float*)d_in[9];
    const float* bo = (const float*)d_in[10];
    float* out = (float*)d_out;

    cudaFuncSetAttribute(gemm_qkv, cudaFuncAttributeMaxDynamicSharedMemorySize, GEMM_SMEM_BYTES);
    cudaFuncSetAttribute(gemm_out, cudaFuncAttributeMaxDynamicSharedMemorySize, O_SMEM_BYTES);
    cudaFuncSetAttribute(flash_attn_mma, cudaFuncAttributeMaxDynamicSharedMemorySize, ATTN_SMEM_BYTES);

    round_pre<<<(PRE_TOTAL + 255) / 256, 256>>>(q, k, v, wq, wk, wv, wo);

    gemm_qkv<<<dim3(DMODEL / 128, S_LEN / 128, 3), 256, GEMM_SMEM_BYTES>>>(bq, bk, bv);

    flash_attn_mma<<<dim3(S_LEN / 64, NHEADS), 128, ATTN_SMEM_BYTES>>>();

    gemm_out<<<dim3(DMODEL / 128, S_LEN / 64), 256, O_SMEM_BYTES>>>(bo, out);
}

// round 8
// speedup vs baseline: 8.1901x; 1.9448x over previous
#include <cuda_runtime.h>
#include <cuda_fp16.h>
#include <cstdint>
#include <math.h>

#define S_LEN 4096
#define DMODEL 768
#define NHEADS 12
#define DHEAD 64

// Scratch (static device globals — no allocation allowed)
__device__ __half g_Qh[NHEADS * S_LEN * DHEAD];   // [h][s][d] fp16(0.125*qproj)
__device__ __half g_Kh[NHEADS * S_LEN * DHEAD];   // [h][s][d] fp16
__device__ __half g_Vt[NHEADS * DHEAD * S_LEN];   // [h][d][s] fp16 transposed
__device__ __half g_Ctx[S_LEN * DMODEL];          // [s][dmodel] fp16
// fp16 copies of inputs/weights
__device__ __half g_Aq[S_LEN * DMODEL];
__device__ __half g_Ak[S_LEN * DMODEL];
__device__ __half g_Av[S_LEN * DMODEL];
__device__ __half g_Wq[DMODEL * DMODEL];
__device__ __half g_Wk[DMODEL * DMODEL];
__device__ __half g_Wv[DMODEL * DMODEL];
__device__ __half g_Wo[DMODEL * DMODEL];

// ---------------------------------------------------------------------------
// PTX helpers (sm_80-era PTX only — compute_103 baseline-safe)
// ---------------------------------------------------------------------------
__device__ __forceinline__ uint32_t smem_u32(const void* p) {
    uint32_t a;
    asm("{ .reg .u64 t; cvta.to.shared.u64 t, %1; cvt.u32.u64 %0, t; }"
        : "=r"(a) : "l"(p));
    return a;
}

#define CP_ASYNC16(dst, src) \
    asm volatile("cp.async.cg.shared.global [%0], [%1], 16;" \
                 :: "r"(dst), "l"(src))
#define CP_COMMIT() asm volatile("cp.async.commit_group;" ::: "memory")
#define CP_WAIT3()  asm volatile("cp.async.wait_group 3;" ::: "memory")
#define CP_WAIT2()  asm volatile("cp.async.wait_group 2;" ::: "memory")
#define CP_WAIT0()  asm volatile("cp.async.wait_group 0;" ::: "memory")

__device__ __forceinline__ void ldsm_x4(uint32_t* r, uint32_t addr) {
    asm volatile("ldmatrix.sync.aligned.m8n8.x4.shared.b16 {%0,%1,%2,%3}, [%4];"
                 : "=r"(r[0]), "=r"(r[1]), "=r"(r[2]), "=r"(r[3]) : "r"(addr));
}
__device__ __forceinline__ void mma_f16(float* c, const uint32_t* a, const uint32_t* b) {
    asm volatile(
        "mma.sync.aligned.m16n8k16.row.col.f32.f16.f16.f32 "
        "{%0,%1,%2,%3}, {%4,%5,%6,%7}, {%8,%9}, {%0,%1,%2,%3};"
        : "+f"(c[0]), "+f"(c[1]), "+f"(c[2]), "+f"(c[3])
        : "r"(a[0]), "r"(a[1]), "r"(a[2]), "r"(a[3]), "r"(b[0]), "r"(b[1]));
}
__device__ __forceinline__ void sts32u(uint32_t a, uint32_t x) {
    asm volatile("st.shared.b32 [%0], %1;" :: "r"(a), "r"(x));
}
__device__ __forceinline__ uint32_t packh2(float x, float y) {
    __half2 h = __floats2half2_rn(x, y);
    return *(uint32_t*)&h;
}

// ---------------------------------------------------------------------------
// Pre-convert pass: f32 -> f16 for inputs and weights (memory bound)
// ---------------------------------------------------------------------------
#define NA8 (S_LEN * DMODEL / 8)      // 393216
#define NW8 (DMODEL * DMODEL / 8)     // 73728
#define PRE_TOTAL (3 * NA8 + 4 * NW8)

__global__ __launch_bounds__(256)
void round_pre(const float* __restrict__ q, const float* __restrict__ k,
               const float* __restrict__ v,
               const float* __restrict__ wq, const float* __restrict__ wk,
               const float* __restrict__ wv, const float* __restrict__ wo)
{
    int idx = blockIdx.x * 256 + threadIdx.x;
    if (idx >= PRE_TOTAL) return;
    const float* src;
    __half* dst;
    int local;
    if (idx < 3 * NA8) {
        int t = idx / NA8;
        local = idx - t * NA8;
        src = (t == 0) ? q : (t == 1) ? k : v;
        dst = (t == 0) ? g_Aq : (t == 1) ? g_Ak : g_Av;
    } else {
        int j = idx - 3 * NA8;
        int t = j / NW8;
        local = j - t * NW8;
        src = (t == 0) ? wq : (t == 1) ? wk : (t == 2) ? wv : wo;
        dst = (t == 0) ? g_Wq : (t == 1) ? g_Wk : (t == 2) ? g_Wv : g_Wo;
    }
    const float4* s4 = (const float4*)src + local * 2;
    float4 x0 = s4[0], x1 = s4[1];
    uint4 o;
    o.x = packh2(x0.x, x0.y);
    o.y = packh2(x0.z, x0.w);
    o.z = packh2(x1.x, x1.y);
    o.w = packh2(x1.z, x1.w);
    ((uint4*)dst)[local] = o;
}

// ---------------------------------------------------------------------------
// FP16 tensor-core GEMM core: C = A @ B^T, A/B fp16 [rows][768].
// Tile 128x128, BK=32 (24 k-tiles), 256 threads (8 warps 2m x 4n).
// Rows padded to 80B -> conflict-free ldsm. 4-stage cp.async, 1 barrier/tile.
// ---------------------------------------------------------------------------
#define ROWB 80
#define HALF_STAGE_BYTES (128 * ROWB)        // 10240
#define STAGE_BYTES (2 * HALF_STAGE_BYTES)   // 20480
#define NSTAGE 4
#define GEMM_SMEM_BYTES (NSTAGE * STAGE_BYTES)  // 81920
#define KT_TILES 24                          // 768 / 32

struct GemmFrag {
    float acc[4][4][4];
};

__device__ __forceinline__ void gemm_core(const __half* __restrict__ A,
                                          const __half* __restrict__ B,
                                          int m0, int n0, GemmFrag& F)
{
    extern __shared__ float sm[];
    const uint32_t sbase = smem_u32(sm);
    const int tid  = threadIdx.x;
    const int lane = tid & 31;
    const int wid  = tid >> 5;
    const int warp_m = (wid & 1) * 64;
    const int warp_n = (wid >> 1) * 32;

    const char* gA = (const char*)(A + (size_t)m0 * DMODEL);
    const char* gB = (const char*)(B + (size_t)n0 * DMODEL);

    auto issue = [&](int kt) {
        int stage = kt & (NSTAGE - 1);
        uint32_t dstBase = sbase + stage * STAGE_BYTES;
#pragma unroll
        for (int c = 0; c < 4; c++) {
            int idx = tid + c * 256;        // 0..1023
            int mat = idx >> 9;
            int i   = idx & 511;
            int row = i >> 2;               // 0..127
            int ch  = i & 3;                // 16B chunk (64B row data)
            uint32_t dst = dstBase + mat * HALF_STAGE_BYTES + row * ROWB + ch * 16;
            const char* src = (mat ? gB : gA) + (size_t)row * 1536 + (size_t)kt * 64 + ch * 16;
            CP_ASYNC16(dst, src);
        }
    };

#pragma unroll
    for (int i = 0; i < 4; i++)
#pragma unroll
        for (int j = 0; j < 4; j++)
#pragma unroll
            for (int r = 0; r < 4; r++) F.acc[i][j][r] = 0.f;

    issue(0); CP_COMMIT();
    issue(1); CP_COMMIT();
    issue(2); CP_COMMIT();

    const int a_row  = lane & 15;
    const int a_ch   = (lane >> 4) & 1;
    const int b_row  = lane & 7;
    const int b_half = (lane >> 3) & 1;
    const int b_pair = (lane >> 4) & 1;

    for (int kt = 0; kt < KT_TILES; kt++) {
        CP_WAIT2();
        __syncthreads();
        if (kt + 3 < KT_TILES) issue(kt + 3);
        CP_COMMIT();

        uint32_t aS = sbase + (kt & (NSTAGE - 1)) * STAGE_BYTES;
        uint32_t bS = aS + HALF_STAGE_BYTES;

#pragma unroll
        for (int ks = 0; ks < 2; ks++) {       // two k16 steps per BK=32
            uint32_t a[4][4], b[4][2];
#pragma unroll
            for (int am = 0; am < 4; am++) {
                uint32_t addr = aS + (warp_m + am * 16 + a_row) * ROWB
                              + ks * 32 + a_ch * 16;
                ldsm_x4(a[am], addr);
            }
#pragma unroll
            for (int bp = 0; bp < 2; bp++) {
                uint32_t t4[4];
                uint32_t addr = bS + (warp_n + (bp * 2 + b_pair) * 8 + b_row) * ROWB
                              + ks * 32 + b_half * 16;
                ldsm_x4(t4, addr);
                b[bp * 2 + 0][0] = t4[0]; b[bp * 2 + 0][1] = t4[1];
                b[bp * 2 + 1][0] = t4[2]; b[bp * 2 + 1][1] = t4[3];
            }
#pragma unroll
            for (int am = 0; am < 4; am++)
#pragma unroll
                for (int bn = 0; bn < 4; bn++)
                    mma_f16(F.acc[am][bn], a[am], b[bn]);
        }
    }
}

// Fused Q/K/V projections. z=0: Q (scaled) -> g_Qh. z=1: K -> g_Kh. z=2: V -> g_Vt.
__global__ __launch_bounds__(256)
void gemm_qkv(const float* __restrict__ bq, const float* __restrict__ bk,
              const float* __restrict__ bv)
{
    const int z = blockIdx.z;
    const __half* A    = (z == 0) ? g_Aq : (z == 1) ? g_Ak : g_Av;
    const __half* W    = (z == 0) ? g_Wq : (z == 1) ? g_Wk : g_Wv;
    const float* bias  = (z == 0) ? bq : (z == 1) ? bk : bv;

    const int m0 = blockIdx.y * 128;
    const int n0 = blockIdx.x * 128;

    GemmFrag F;
    gemm_core(A, W, m0, n0, F);

    const int lane = threadIdx.x & 31;
    const int wid  = threadIdx.x >> 5;
    const int warp_m = (wid & 1) * 64;
    const int warp_n = (wid >> 1) * 32;
    const int g   = lane >> 2;
    const int tig = lane & 3;

#pragma unroll
    for (int am = 0; am < 4; am++) {
#pragma unroll
        for (int bn = 0; bn < 4; bn++) {
            int ncol = n0 + warp_n + bn * 8 + tig * 2;
            float2 bz = *(const float2*)(bias + ncol);
            int hd = ncol >> 6;
            int d  = ncol & 63;
#pragma unroll
            for (int h = 0; h < 2; h++) {
                int m = m0 + warp_m + am * 16 + g + h * 8;
                float ox = F.acc[am][bn][h * 2 + 0] + bz.x;
                float oy = F.acc[am][bn][h * 2 + 1] + bz.y;
                if (z == 0) {
                    *(uint32_t*)(g_Qh + ((size_t)hd * S_LEN + m) * DHEAD + d) =
                        packh2(ox * 0.125f, oy * 0.125f);
                } else if (z == 1) {
                    *(uint32_t*)(g_Kh + ((size_t)hd * S_LEN + m) * DHEAD + d) =
                        packh2(ox, oy);
                } else {
                    g_Vt[((size_t)hd * DHEAD + d)     * S_LEN + m] = __float2half_rn(ox);
                    g_Vt[((size_t)hd * DHEAD + d + 1) * S_LEN + m] = __float2half_rn(oy);
                }
            }
        }
    }
}

// ---------------------------------------------------------------------------
// Output projection: g_Ctx (fp16) @ g_Wo^T + bo -> fp32 out. 64x128 tiles.
// ---------------------------------------------------------------------------
#define O_A_BYTES (64 * ROWB)                       // 5120
#define O_STAGE_BYTES (O_A_BYTES + HALF_STAGE_BYTES)  // 15360
#define O_SMEM_BYTES (NSTAGE * O_STAGE_BYTES)       // 61440

__global__ __launch_bounds__(256)
void gemm_out(const float* __restrict__ bo, float* __restrict__ Out)
{
    extern __shared__ float sm[];
    const uint32_t sbase = smem_u32(sm);
    const int tid  = threadIdx.x;
    const int lane = tid & 31;
    const int wid  = tid >> 5;
    const int m0 = blockIdx.y * 64;
    const int n0 = blockIdx.x * 128;
    const int warp_n = wid * 16;

    const char* gA = (const char*)(g_Ctx + (size_t)m0 * DMODEL);
    const char* gB = (const char*)(g_Wo + (size_t)n0 * DMODEL);

    auto issue = [&](int kt) {
        int stage = kt & (NSTAGE - 1);
        uint32_t dstBase = sbase + stage * O_STAGE_BYTES;
#pragma unroll
        for (int c = 0; c < 3; c++) {
            int idx = tid + c * 256;            // 0..767
            if (idx < 256) {                    // A: 64 rows x 4 chunks
                int row = idx >> 2;
                int ch  = idx & 3;
                CP_ASYNC16(dstBase + row * ROWB + ch * 16,
                           gA + (size_t)row * 1536 + (size_t)kt * 64 + ch * 16);
            } else {                            // B: 128 rows x 4 chunks
                int j = idx - 256;
                int row = j >> 2;
                int ch  = j & 3;
                CP_ASYNC16(dstBase + O_A_BYTES + row * ROWB + ch * 16,
                           gB + (size_t)row * 1536 + (size_t)kt * 64 + ch * 16);
            }
        }
    };

    float acc[4][2][4];
#pragma unroll
    for (int i = 0; i < 4; i++)
#pragma unroll
        for (int j = 0; j < 2; j++)
#pragma unroll
            for (int r = 0; r < 4; r++) acc[i][j][r] = 0.f;

    issue(0); CP_COMMIT();
    issue(1); CP_COMMIT();
    issue(2); CP_COMMIT();

    const int a_row  = lane & 15;
    const int a_ch   = (lane >> 4) & 1;
    const int b_row  = lane & 7;
    const int b_half = (lane >> 3) & 1;
    const int b_pair = (lane >> 4) & 1;

    for (int kt = 0; kt < KT_TILES; kt++) {
        CP_WAIT2();
        __syncthreads();
        if (kt + 3 < KT_TILES) issue(kt + 3);
        CP_COMMIT();

        uint32_t aS = sbase + (kt & (NSTAGE - 1)) * O_STAGE_BYTES;
        uint32_t bS = aS + O_A_BYTES;

#pragma unroll
        for (int ks = 0; ks < 2; ks++) {
            uint32_t a[4][4], b[2][2];
#pragma unroll
            for (int am = 0; am < 4; am++) {
                uint32_t addr = aS + (am * 16 + a_row) * ROWB + ks * 32 + a_ch * 16;
                ldsm_x4(a[am], addr);
            }
            {
                uint32_t t4[4];
                uint32_t addr = bS + (warp_n + b_pair * 8 + b_row) * ROWB
                              + ks * 32 + b_half * 16;
                ldsm_x4(t4, addr);
                b[0][0] = t4[0]; b[0][1] = t4[1];
                b[1][0] = t4[2]; b[1][1] = t4[3];
            }
#pragma unroll
            for (int am = 0; am < 4; am++)
#pragma unroll
                for (int bn = 0; bn < 2; bn++)
                    mma_f16(acc[am][bn], a[am], b[bn]);
        }
    }

    const int g   = lane >> 2;
    const int tig = lane & 3;
#pragma unroll
    for (int am = 0; am < 4; am++) {
#pragma unroll
        for (int bn = 0; bn < 2; bn++) {
            int ncol = n0 + warp_n + bn * 8 + tig * 2;
            float2 bz = *(const float2*)(bo + ncol);
#pragma unroll
            for (int h = 0; h < 2; h++) {
                int m = m0 + am * 16 + g + h * 8;
                float2 o;
                o.x = acc[am][bn][h * 2 + 0] + bz.x;
                o.y = acc[am][bn][h * 2 + 1] + bz.y;
                *(float2*)(Out + (size_t)m * DMODEL + ncol) = o;
            }
        }
    }
}

// ---------------------------------------------------------------------------
// FP16 tensor-core flash attention (causal), software-pipelined.
// BM=64, BN=64, 128 threads (4 warps). fp16 tiles: rows 128B + 16B pad.
// smem 45KB -> 3 CTAs/SM.
// ---------------------------------------------------------------------------
#define KS_ROWB 144
#define KS_STG  (64 * KS_ROWB)          // 9216
#define OFF_KS0 0
#define OFF_KS1 (OFF_KS0 + KS_STG)
#define OFF_VT0 (OFF_KS1 + KS_STG)
#define OFF_VT1 (OFF_VT0 + KS_STG)
#define OFF_PS  (OFF_VT1 + KS_STG)
#define ATTN_SMEM_BYTES (OFF_PS + KS_STG)   // 46080

__global__ __launch_bounds__(128, 3)
void flash_attn_mma()
{
    extern __shared__ char smc[];
    const uint32_t sb = smem_u32(smc);
    const int tid  = threadIdx.x;
    const int lane = tid & 31;
    const int w    = tid >> 5;
    const int head = blockIdx.y;
    const int qb   = gridDim.x - 1 - blockIdx.x;   // biggest workload first
    const int q0   = qb * 64;

    const __half* Qg = g_Qh + (size_t)head * S_LEN * DHEAD;
    const __half* Kg = g_Kh + (size_t)head * S_LEN * DHEAD;
    const __half* Vt = g_Vt + (size_t)head * DHEAD * S_LEN;

    const int ntiles = qb + 1;

    // ---- group 1: Q tile -> PS via cp.async (64 rows x 128B) ----
#pragma unroll
    for (int p = 0; p < 4; p++) {
        int e   = tid + p * 128;        // 0..511
        int row = e >> 3;
        int ch  = e & 7;
        CP_ASYNC16(sb + OFF_PS + row * KS_ROWB + ch * 16,
                   (const char*)Qg + (size_t)(q0 + row) * 128 + ch * 16);
    }
    CP_COMMIT();

    auto issue_K = [&](int t) {
        uint32_t ksB = sb + ((t & 1) ? OFF_KS1 : OFF_KS0);
        int kv0 = t * 64;
#pragma unroll
        for (int c = 0; c < 4; c++) {
            int j = tid + c * 128;
            int row = j >> 3;
            int ch  = j & 7;
            CP_ASYNC16(ksB + row * KS_ROWB + ch * 16,
                       (const char*)Kg + (size_t)(kv0 + row) * 128 + ch * 16);
        }
    };
    auto issue_V = [&](int t) {
        uint32_t vtB = sb + ((t & 1) ? OFF_VT1 : OFF_VT0);
        int kv0 = t * 64;
#pragma unroll
        for (int c = 0; c < 4; c++) {
            int j = tid + c * 128;
            int row = j >> 3;               // d index
            int ch  = j & 7;
            CP_ASYNC16(vtB + row * KS_ROWB + ch * 16,
                       (const char*)Vt + (size_t)row * (S_LEN * 2) + (size_t)kv0 * 2 + ch * 16);
        }
    };

    // groups 2..4: K0, K1, V0
    issue_K(0); CP_COMMIT();
    if (ntiles > 1) issue_K(1);
    CP_COMMIT();
    issue_V(0); CP_COMMIT();

    // ---- Q fragments ----
    CP_WAIT3();            // Q done
    __syncthreads();

    const int a_row = lane & 15;
    const int a_ch  = (lane >> 4) & 1;
    const uint32_t aAddrBase = sb + OFF_PS + (w * 16 + a_row) * KS_ROWB + a_ch * 16;

    uint32_t qh[4][4];
#pragma unroll
    for (int kb = 0; kb < 4; kb++)
        ldsm_x4(qh[kb], aAddrBase + kb * 32);

    float m_[2] = {-1e30f, -1e30f};
    float l_[2] = {0.f, 0.f};
    float o[8][4];
#pragma unroll
    for (int nb = 0; nb < 8; nb++)
#pragma unroll
        for (int j = 0; j < 4; j++) o[nb][j] = 0.f;

    CP_WAIT2();            // K0 done (K1, V0 in flight)
    __syncthreads();

    const int b_nboff = ((lane >> 4) & 1) * 8;
    const int b_row   = lane & 7;
    const int b_half  = (lane >> 3) & 1;
    const int g       = lane >> 2;
    const int tg      = lane & 3;

    // ---- prologue: S_0 = Q K_0 ----
    float s[8][4];
#pragma unroll
    for (int nb = 0; nb < 8; nb++)
#pragma unroll
        for (int j = 0; j < 4; j++) s[nb][j] = 0.f;
    {
        uint32_t ksS = sb + OFF_KS0;
#pragma unroll
        for (int kb = 0; kb < 4; kb++) {
            uint32_t bh[16];
#pragma unroll
            for (int bp = 0; bp < 4; bp++) {
                uint32_t roff = (bp * 16 + b_nboff + b_row) * KS_ROWB + kb * 32 + b_half * 16;
                ldsm_x4(&bh[bp * 4], ksS + roff);
            }
#pragma unroll
            for (int nb = 0; nb < 8; nb++)
                mma_f16(s[nb], qh[kb], &bh[nb * 2]);
        }
    }

    for (int t = 0; t < ntiles; t++) {
        CP_WAIT0();          // K_{t+1}, V_t complete
        __syncthreads();
        if (t + 2 < ntiles) issue_K(t + 2);
        CP_COMMIT();
        if (t + 1 < ntiles) issue_V(t + 1);
        CP_COMMIT();

        const bool do_qk = (t + 1 < ntiles);
        uint32_t ksN = sb + (((t + 1) & 1) ? OFF_KS1 : OFF_KS0);
        uint32_t vtS = sb + ((t & 1) ? OFF_VT1 : OFF_VT0);

        // ---- causal mask (diagonal tile only) ----
        if (t == qb) {
            int kv0 = t * 64;
            int qa = q0 + w * 16 + g;
#pragma unroll
            for (int nb = 0; nb < 8; nb++) {
#pragma unroll
                for (int j = 0; j < 4; j++) {
                    int col = kv0 + nb * 8 + 2 * tg + (j & 1);
                    int row = qa + (j >> 1) * 8;
                    if (col > row) s[nb][j] = -1e30f;
                }
            }
        }

        // ---- online softmax (rows g and g+8) ----
#pragma unroll
        for (int r = 0; r < 2; r++) {
            float mx = m_[r];
#pragma unroll
            for (int nb = 0; nb < 8; nb++)
                mx = fmaxf(mx, fmaxf(s[nb][2 * r], s[nb][2 * r + 1]));
            mx = fmaxf(mx, __shfl_xor_sync(0xffffffffu, mx, 1));
            mx = fmaxf(mx, __shfl_xor_sync(0xffffffffu, mx, 2));
            float esc = __expf(m_[r] - mx);
            float sum = 0.f;
#pragma unroll
            for (int nb = 0; nb < 8; nb++) {
#pragma unroll
                for (int jj = 0; jj < 2; jj++) {
                    float p = __expf(s[nb][2 * r + jj] - mx);
                    s[nb][2 * r + jj] = p;
                    sum += p;
                }
            }
            sum += __shfl_xor_sync(0xffffffffu, sum, 1);
            sum += __shfl_xor_sync(0xffffffffu, sum, 2);
            l_[r] = l_[r] * esc + sum;
            m_[r] = mx;
#pragma unroll
            for (int nb = 0; nb < 8; nb++) {
                o[nb][2 * r]     *= esc;
                o[nb][2 * r + 1] *= esc;
            }
        }

        // ---- stage P_t (fp16) in warp-private Ps rows ----
        uint32_t psW = sb + OFF_PS + (w * 16 + g) * KS_ROWB + tg * 4;
#pragma unroll
        for (int nb = 0; nb < 8; nb++) {
            sts32u(psW + nb * 16, packh2(s[nb][0], s[nb][1]));
            sts32u(psW + 8 * KS_ROWB + nb * 16, packh2(s[nb][2], s[nb][3]));
        }
        __syncwarp();

        if (do_qk) {
#pragma unroll
            for (int nb = 0; nb < 8; nb++)
#pragma unroll
                for (int j = 0; j < 4; j++) s[nb][j] = 0.f;
        }

        // ---- interleaved: S_{t+1} = Q K_{t+1}  +  O += P_t V_t ----
#pragma unroll
        for (int u = 0; u < 4; u++) {
            if (do_qk) {
                uint32_t bh[16];
#pragma unroll
                for (int bp = 0; bp < 4; bp++) {
                    uint32_t roff = (bp * 16 + b_nboff + b_row) * KS_ROWB
                                  + u * 32 + b_half * 16;
                    ldsm_x4(&bh[bp * 4], ksN + roff);
                }
#pragma unroll
                for (int nb = 0; nb < 8; nb++)
                    mma_f16(s[nb], qh[u], &bh[nb * 2]);
            }
            {
                uint32_t pa[4];
                ldsm_x4(pa, aAddrBase + u * 32);
                uint32_t bb[16];
#pragma unroll
                for (int bp = 0; bp < 4; bp++) {
                    uint32_t roff = (bp * 16 + b_nboff + b_row) * KS_ROWB
                                  + u * 32 + b_half * 16;
                    ldsm_x4(&bb[bp * 4], vtS + roff);
                }
#pragma unroll
                for (int nb = 0; nb < 8; nb++)
                    mma_f16(o[nb], pa, &bb[nb * 2]);
            }
        }
    }

    // ---- epilogue: normalize, write fp16 context [s][dmodel] ----
#pragma unroll
    for (int r = 0; r < 2; r++) {
        float inv = 1.f / l_[r];
        int qrow = q0 + w * 16 + g + r * 8;
        __half* dst = g_Ctx + (size_t)qrow * DMODEL + head * DHEAD + 2 * tg;
#pragma unroll
        for (int nb = 0; nb < 8; nb++) {
            *(uint32_t*)(dst + nb * 8) =
                packh2(o[nb][2 * r] * inv, o[nb][2 * r + 1] * inv);
        }
    }
}

// ---------------------------------------------------------------------------
extern "C" void kernel_launch(void* const* d_in, const int* in_sizes, int n_in,
                              void* d_out, int out_size)
{
    const float* q  = (const float*)d_in[0];
    const float* k  = (const float*)d_in[1];
    const float* v  = (const float*)d_in[2];
    const float* wq = (const float*)d_in[3];
    const float* bq = (const float*)d_in[4];
    const float* wk = (const float*)d_in[5];
    const float* bk = (const float*)d_in[6];
    const float* wv = (const float*)d_in[7];
    const float* bv = (const float*)d_in[8];
    const float* wo = (const float*)d_in[9];
    const float* bo = (const float*)d_in[10];
    float* out = (float*)d_out;

    cudaFuncSetAttribute(gemm_qkv, cudaFuncAttributeMaxDynamicSharedMemorySize, GEMM_SMEM_BYTES);
    cudaFuncSetAttribute(gemm_out, cudaFuncAttributeMaxDynamicSharedMemorySize, O_SMEM_BYTES);
    cudaFuncSetAttribute(flash_attn_mma, cudaFuncAttributeMaxDynamicSharedMemorySize, ATTN_SMEM_BYTES);

    round_pre<<<(PRE_TOTAL + 255) / 256, 256>>>(q, k, v, wq, wk, wv, wo);

    gemm_qkv<<<dim3(DMODEL / 128, S_LEN / 128, 3), 256, GEMM_SMEM_BYTES>>>(bq, bk, bv);

    flash_attn_mma<<<dim3(S_LEN / 64, NHEADS), 128, ATTN_SMEM_BYTES>>>();

    gemm_out<<<dim3(DMODEL / 128, S_LEN / 64), 256, O_SMEM_BYTES>>>(bo, out);
}

// round 9
// speedup vs baseline: 8.3459x; 1.0190x over previous
#include <cuda_runtime.h>
#include <cuda_fp16.h>
#include <cstdint>
#include <math.h>

#define S_LEN 4096
#define DMODEL 768
#define NHEADS 12
#define DHEAD 64

// Scratch (static device globals — no allocation allowed)
__device__ __half g_Qh[NHEADS * S_LEN * DHEAD];   // [h][s][d] fp16(0.125*log2e*qproj)
__device__ __half g_Kh[NHEADS * S_LEN * DHEAD];   // [h][s][d] fp16
__device__ __half g_Vh[NHEADS * S_LEN * DHEAD];   // [h][s][d] fp16 (natural)
__device__ __half g_Ctx[S_LEN * DMODEL];          // [s][dmodel] fp16
// fp16 copies of inputs/weights
__device__ __half g_Aq[S_LEN * DMODEL];
__device__ __half g_Ak[S_LEN * DMODEL];
__device__ __half g_Av[S_LEN * DMODEL];
__device__ __half g_Wq[DMODEL * DMODEL];
__device__ __half g_Wk[DMODEL * DMODEL];
__device__ __half g_Wv[DMODEL * DMODEL];
__device__ __half g_Wo[DMODEL * DMODEL];

#define QSCALE 0.1803368801111214f   // 0.125 * log2(e)

// ---------------------------------------------------------------------------
// PTX helpers (sm_80-era PTX only — compute_103 baseline-safe)
// ---------------------------------------------------------------------------
__device__ __forceinline__ uint32_t smem_u32(const void* p) {
    uint32_t a;
    asm("{ .reg .u64 t; cvta.to.shared.u64 t, %1; cvt.u32.u64 %0, t; }"
        : "=r"(a) : "l"(p));
    return a;
}

#define CP_ASYNC16(dst, src) \
    asm volatile("cp.async.cg.shared.global [%0], [%1], 16;" \
                 :: "r"(dst), "l"(src))
#define CP_COMMIT() asm volatile("cp.async.commit_group;" ::: "memory")
#define CP_WAIT3()  asm volatile("cp.async.wait_group 3;" ::: "memory")
#define CP_WAIT2()  asm volatile("cp.async.wait_group 2;" ::: "memory")
#define CP_WAIT0()  asm volatile("cp.async.wait_group 0;" ::: "memory")

__device__ __forceinline__ void ldsm_x4(uint32_t* r, uint32_t addr) {
    asm volatile("ldmatrix.sync.aligned.m8n8.x4.shared.b16 {%0,%1,%2,%3}, [%4];"
                 : "=r"(r[0]), "=r"(r[1]), "=r"(r[2]), "=r"(r[3]) : "r"(addr));
}
__device__ __forceinline__ void ldsm_x4t(uint32_t* r, uint32_t addr) {
    asm volatile("ldmatrix.sync.aligned.m8n8.x4.trans.shared.b16 {%0,%1,%2,%3}, [%4];"
                 : "=r"(r[0]), "=r"(r[1]), "=r"(r[2]), "=r"(r[3]) : "r"(addr));
}
__device__ __forceinline__ void mma_f16(float* c, const uint32_t* a, const uint32_t* b) {
    asm volatile(
        "mma.sync.aligned.m16n8k16.row.col.f32.f16.f16.f32 "
        "{%0,%1,%2,%3}, {%4,%5,%6,%7}, {%8,%9}, {%0,%1,%2,%3};"
        : "+f"(c[0]), "+f"(c[1]), "+f"(c[2]), "+f"(c[3])
        : "r"(a[0]), "r"(a[1]), "r"(a[2]), "r"(a[3]), "r"(b[0]), "r"(b[1]));
}
__device__ __forceinline__ uint32_t packh2(float x, float y) {
    __half2 h = __floats2half2_rn(x, y);
    return *(uint32_t*)&h;
}
__device__ __forceinline__ uint32_t h2exp2u(uint32_t x) {
    uint32_t r;
    asm("ex2.approx.f16x2 %0, %1;" : "=r"(r) : "r"(x));
    return r;
}

// ---------------------------------------------------------------------------
// Pre-convert pass: f32 -> f16 for inputs and weights (memory bound)
// ---------------------------------------------------------------------------
#define NA8 (S_LEN * DMODEL / 8)
#define NW8 (DMODEL * DMODEL / 8)
#define PRE_TOTAL (3 * NA8 + 4 * NW8)

__global__ __launch_bounds__(256)
void round_pre(const float* __restrict__ q, const float* __restrict__ k,
               const float* __restrict__ v,
               const float* __restrict__ wq, const float* __restrict__ wk,
               const float* __restrict__ wv, const float* __restrict__ wo)
{
    int idx = blockIdx.x * 256 + threadIdx.x;
    if (idx >= PRE_TOTAL) return;
    const float* src;
    __half* dst;
    int local;
    if (idx < 3 * NA8) {
        int t = idx / NA8;
        local = idx - t * NA8;
        src = (t == 0) ? q : (t == 1) ? k : v;
        dst = (t == 0) ? g_Aq : (t == 1) ? g_Ak : g_Av;
    } else {
        int j = idx - 3 * NA8;
        int t = j / NW8;
        local = j - t * NW8;
        src = (t == 0) ? wq : (t == 1) ? wk : (t == 2) ? wv : wo;
        dst = (t == 0) ? g_Wq : (t == 1) ? g_Wk : (t == 2) ? g_Wv : g_Wo;
    }
    const float4* s4 = (const float4*)src + local * 2;
    float4 x0 = s4[0], x1 = s4[1];
    uint4 o;
    o.x = packh2(x0.x, x0.y);
    o.y = packh2(x0.z, x0.w);
    o.z = packh2(x1.x, x1.y);
    o.w = packh2(x1.z, x1.w);
    ((uint4*)dst)[local] = o;
}

// ---------------------------------------------------------------------------
// FP16 GEMM 64x128 tile core pieces (BK=32, 24 k-tiles, 256 threads, 8 warps,
// each warp: 64m x 16n). Rows padded to 80B. 4-stage cp.async, 1 barrier/tile.
// ---------------------------------------------------------------------------
#define ROWB 80
#define B_TILE_BYTES (128 * ROWB)                  // 10240
#define A_TILE_BYTES (64 * ROWB)                   // 5120
#define G_STAGE_BYTES (A_TILE_BYTES + B_TILE_BYTES)  // 15360
#define NSTAGE 4
#define GEMM_SMEM_BYTES (NSTAGE * G_STAGE_BYTES)   // 61440
#define KT_TILES 24

#define GEMM64_CORE(A_PTR, B_PTR, ACC)                                         \
    extern __shared__ float sm[];                                              \
    const uint32_t sbase = smem_u32(sm);                                       \
    const int tid  = threadIdx.x;                                              \
    const int lane = tid & 31;                                                 \
    const int wid  = tid >> 5;                                                 \
    const int warp_n = wid * 16;                                               \
    const char* gA = (const char*)(A_PTR);                                     \
    const char* gB = (const char*)(B_PTR);                                     \
    auto issue = [&](int kt) {                                                 \
        int stage = kt & (NSTAGE - 1);                                         \
        uint32_t dstBase = sbase + stage * G_STAGE_BYTES;                      \
        _Pragma("unroll")                                                      \
        for (int c = 0; c < 3; c++) {                                          \
            int idx = tid + c * 256;                                           \
            if (idx < 256) {                                                   \
                int row = idx >> 2, ch = idx & 3;                              \
                CP_ASYNC16(dstBase + row * ROWB + ch * 16,                     \
                           gA + (size_t)row * 1536 + (size_t)kt * 64 + ch * 16); \
            } else {                                                           \
                int j = idx - 256;                                             \
                int row = j >> 2, ch = j & 3;                                  \
                CP_ASYNC16(dstBase + A_TILE_BYTES + row * ROWB + ch * 16,      \
                           gB + (size_t)row * 1536 + (size_t)kt * 64 + ch * 16); \
            }                                                                  \
        }                                                                      \
    };                                                                         \
    _Pragma("unroll")                                                          \
    for (int i = 0; i < 4; i++)                                                \
        _Pragma("unroll")                                                      \
        for (int j = 0; j < 2; j++)                                            \
            _Pragma("unroll")                                                  \
            for (int r = 0; r < 4; r++) ACC[i][j][r] = 0.f;                    \
    issue(0); CP_COMMIT();                                                     \
    issue(1); CP_COMMIT();                                                     \
    issue(2); CP_COMMIT();                                                     \
    const int a_row  = lane & 15;                                              \
    const int a_ch   = (lane >> 4) & 1;                                        \
    const int b_row  = lane & 7;                                               \
    const int b_half = (lane >> 3) & 1;                                        \
    const int b_pair = (lane >> 4) & 1;                                        \
    for (int kt = 0; kt < KT_TILES; kt++) {                                    \
        CP_WAIT2();                                                            \
        __syncthreads();                                                       \
        if (kt + 3 < KT_TILES) issue(kt + 3);                                  \
        CP_COMMIT();                                                           \
        uint32_t aS = sbase + (kt & (NSTAGE - 1)) * G_STAGE_BYTES;             \
        uint32_t bS = aS + A_TILE_BYTES;                                       \
        _Pragma("unroll")                                                      \
        for (int ks = 0; ks < 2; ks++) {                                       \
            uint32_t a[4][4], b[2][2];                                         \
            _Pragma("unroll")                                                  \
            for (int am = 0; am < 4; am++)                                     \
                ldsm_x4(a[am], aS + (am * 16 + a_row) * ROWB + ks * 32 + a_ch * 16); \
            {                                                                  \
                uint32_t t4[4];                                                \
                ldsm_x4(t4, bS + (warp_n + b_pair * 8 + b_row) * ROWB          \
                            + ks * 32 + b_half * 16);                          \
                b[0][0] = t4[0]; b[0][1] = t4[1];                              \
                b[1][0] = t4[2]; b[1][1] = t4[3];                              \
            }                                                                  \
            _Pragma("unroll")                                                  \
            for (int am = 0; am < 4; am++)                                     \
                _Pragma("unroll")                                              \
                for (int bn = 0; bn < 2; bn++)                                 \
                    mma_f16(ACC[am][bn], a[am], b[bn]);                        \
        }                                                                      \
    }

// Fused Q/K/V projections, 64x128 tiles. z selects projection.
__global__ __launch_bounds__(256)
void gemm_qkv(const float* __restrict__ bq, const float* __restrict__ bk,
              const float* __restrict__ bv)
{
    const int z = blockIdx.z;
    const __half* A   = (z == 0) ? g_Aq : (z == 1) ? g_Ak : g_Av;
    const __half* W   = (z == 0) ? g_Wq : (z == 1) ? g_Wk : g_Wv;
    const float* bias = (z == 0) ? bq : (z == 1) ? bk : bv;
    const int m0 = blockIdx.y * 64;
    const int n0 = blockIdx.x * 128;

    float acc[4][2][4];
    GEMM64_CORE(A + (size_t)m0 * DMODEL, W + (size_t)n0 * DMODEL, acc)

    const int g   = lane >> 2;
    const int tig = lane & 3;
#pragma unroll
    for (int am = 0; am < 4; am++) {
#pragma unroll
        for (int bn = 0; bn < 2; bn++) {
            int ncol = n0 + warp_n + bn * 8 + tig * 2;
            float2 bz = *(const float2*)(bias + ncol);
            int hd = ncol >> 6;
            int d  = ncol & 63;
            __half* base = (z == 0) ? g_Qh : (z == 1) ? g_Kh : g_Vh;
            float sc = (z == 0) ? QSCALE : 1.f;
#pragma unroll
            for (int h = 0; h < 2; h++) {
                int m = m0 + am * 16 + g + h * 8;
                float ox = (acc[am][bn][h * 2 + 0] + bz.x) * sc;
                float oy = (acc[am][bn][h * 2 + 1] + bz.y) * sc;
                *(uint32_t*)(base + ((size_t)hd * S_LEN + m) * DHEAD + d) =
                    packh2(ox, oy);
            }
        }
    }
}

// Output projection: g_Ctx (fp16) @ g_Wo^T + bo -> fp32 out.
__global__ __launch_bounds__(256)
void gemm_out(const float* __restrict__ bo, float* __restrict__ Out)
{
    const int m0 = blockIdx.y * 64;
    const int n0 = blockIdx.x * 128;

    float acc[4][2][4];
    GEMM64_CORE(g_Ctx + (size_t)m0 * DMODEL, g_Wo + (size_t)n0 * DMODEL, acc)

    const int g   = lane >> 2;
    const int tig = lane & 3;
#pragma unroll
    for (int am = 0; am < 4; am++) {
#pragma unroll
        for (int bn = 0; bn < 2; bn++) {
            int ncol = n0 + warp_n + bn * 8 + tig * 2;
            float2 bz = *(const float2*)(bo + ncol);
#pragma unroll
            for (int h = 0; h < 2; h++) {
                int m = m0 + am * 16 + g + h * 8;
                float2 o;
                o.x = acc[am][bn][h * 2 + 0] + bz.x;
                o.y = acc[am][bn][h * 2 + 1] + bz.y;
                *(float2*)(Out + (size_t)m * DMODEL + ncol) = o;
            }
        }
    }
}

// ---------------------------------------------------------------------------
// FP16 flash attention (causal), FA2-style: P kept in registers (C-frag -> A-frag
// repack), V natural via ldmatrix.trans, exp2-domain softmax with ex2.f16x2.
// BM=64, BN=64, 128 threads (4 warps). smem 46KB -> 3+ CTAs/SM.
// ---------------------------------------------------------------------------
#define KS_ROWB 144
#define KS_STG  (64 * KS_ROWB)          // 9216
#define OFF_K0  0
#define OFF_K1  (OFF_K0 + KS_STG)
#define OFF_V0  (OFF_K1 + KS_STG)
#define OFF_V1  (OFF_V0 + KS_STG)
#define OFF_Q   (OFF_V1 + KS_STG)
#define ATTN_SMEM_BYTES (OFF_Q + KS_STG)   // 46080

__global__ __launch_bounds__(128, 3)
void flash_attn_mma()
{
    extern __shared__ char smc[];
    const uint32_t sb = smem_u32(smc);
    const int tid  = threadIdx.x;
    const int lane = tid & 31;
    const int w    = tid >> 5;
    const int head = blockIdx.y;
    const int qb   = gridDim.x - 1 - blockIdx.x;   // biggest workload first
    const int q0   = qb * 64;

    const __half* Qg = g_Qh + (size_t)head * S_LEN * DHEAD;
    const __half* Kg = g_Kh + (size_t)head * S_LEN * DHEAD;
    const __half* Vg = g_Vh + (size_t)head * S_LEN * DHEAD;

    const int ntiles = qb + 1;

    // group 1: Q tile (64 rows x 128B)
#pragma unroll
    for (int p = 0; p < 4; p++) {
        int e   = tid + p * 128;
        int row = e >> 3;
        int ch  = e & 7;
        CP_ASYNC16(sb + OFF_Q + row * KS_ROWB + ch * 16,
                   (const char*)Qg + (size_t)(q0 + row) * 128 + ch * 16);
    }
    CP_COMMIT();

    auto issue_K = [&](int t) {
        uint32_t ksB = sb + ((t & 1) ? OFF_K1 : OFF_K0);
        int kv0 = t * 64;
#pragma unroll
        for (int c = 0; c < 4; c++) {
            int j = tid + c * 128;
            int row = j >> 3;
            int ch  = j & 7;
            CP_ASYNC16(ksB + row * KS_ROWB + ch * 16,
                       (const char*)Kg + (size_t)(kv0 + row) * 128 + ch * 16);
        }
    };
    auto issue_V = [&](int t) {
        uint32_t vB = sb + ((t & 1) ? OFF_V1 : OFF_V0);
        int kv0 = t * 64;
#pragma unroll
        for (int c = 0; c < 4; c++) {
            int j = tid + c * 128;
            int row = j >> 3;
            int ch  = j & 7;
            CP_ASYNC16(vB + row * KS_ROWB + ch * 16,
                       (const char*)Vg + (size_t)(kv0 + row) * 128 + ch * 16);
        }
    };

    issue_K(0); CP_COMMIT();                  // group 2
    if (ntiles > 1) issue_K(1);
    CP_COMMIT();                              // group 3
    issue_V(0); CP_COMMIT();                  // group 4

    CP_WAIT3();            // Q done
    __syncthreads();

    const int a_row = lane & 15;
    const int a_ch  = (lane >> 4) & 1;
    const uint32_t aQ = sb + OFF_Q + (w * 16 + a_row) * KS_ROWB + a_ch * 16;

    uint32_t qh[4][4];
#pragma unroll
    for (int kb = 0; kb < 4; kb++)
        ldsm_x4(qh[kb], aQ + kb * 32);

    float m_[2] = {-1e30f, -1e30f};
    float l_[2] = {0.f, 0.f};
    float o[8][4];
#pragma unroll
    for (int nb = 0; nb < 8; nb++)
#pragma unroll
        for (int j = 0; j < 4; j++) o[nb][j] = 0.f;

    CP_WAIT2();            // K0 done
    __syncthreads();

    const int b_nboff = ((lane >> 4) & 1) * 8;
    const int b_row   = lane & 7;
    const int b_half  = (lane >> 3) & 1;
    const int v_row   = lane & 15;
    const int v_hi    = (lane >> 4) & 1;
    const int g       = lane >> 2;
    const int tg      = lane & 3;

    // prologue: S_0 = Q K_0
    float s[8][4];
#pragma unroll
    for (int nb = 0; nb < 8; nb++)
#pragma unroll
        for (int j = 0; j < 4; j++) s[nb][j] = 0.f;
    {
        uint32_t ksS = sb + OFF_K0;
#pragma unroll
        for (int kb = 0; kb < 4; kb++) {
            uint32_t bh[16];
#pragma unroll
            for (int bp = 0; bp < 4; bp++) {
                uint32_t roff = (bp * 16 + b_nboff + b_row) * KS_ROWB + kb * 32 + b_half * 16;
                ldsm_x4(&bh[bp * 4], ksS + roff);
            }
#pragma unroll
            for (int nb = 0; nb < 8; nb++)
                mma_f16(s[nb], qh[kb], &bh[nb * 2]);
        }
    }

    for (int t = 0; t < ntiles; t++) {
        CP_WAIT0();          // K_{t+1}, V_t complete
        __syncthreads();
        if (t + 2 < ntiles) issue_K(t + 2);
        CP_COMMIT();
        if (t + 1 < ntiles) issue_V(t + 1);
        CP_COMMIT();

        const bool do_qk = (t + 1 < ntiles);
        uint32_t ksN = sb + (((t + 1) & 1) ? OFF_K1 : OFF_K0);
        uint32_t vS  = sb + ((t & 1) ? OFF_V1 : OFF_V0);

        // causal mask (diagonal tile only); scores are in log2 domain
        if (t == qb) {
            int kv0 = t * 64;
            int qa = q0 + w * 16 + g;
#pragma unroll
            for (int nb = 0; nb < 8; nb++) {
#pragma unroll
                for (int j = 0; j < 4; j++) {
                    int col = kv0 + nb * 8 + 2 * tg + (j & 1);
                    int row = qa + (j >> 1) * 8;
                    if (col > row) s[nb][j] = -1e30f;
                }
            }
        }

        // online softmax (base-2). pk[r][nb] = packed fp16 probs = PV A-frags.
        uint32_t pk[2][8];
#pragma unroll
        for (int r = 0; r < 2; r++) {
            float mx = m_[r];
#pragma unroll
            for (int nb = 0; nb < 8; nb++)
                mx = fmaxf(mx, fmaxf(s[nb][2 * r], s[nb][2 * r + 1]));
            mx = fmaxf(mx, __shfl_xor_sync(0xffffffffu, mx, 1));
            mx = fmaxf(mx, __shfl_xor_sync(0xffffffffu, mx, 2));
            float esc = exp2f(m_[r] - mx);
            float sum = 0.f;
#pragma unroll
            for (int nb = 0; nb < 8; nb++) {
                __half2 hx = __floats2half2_rn(s[nb][2 * r] - mx, s[nb][2 * r + 1] - mx);
                uint32_t pe = h2exp2u(*(uint32_t*)&hx);
                pk[r][nb] = pe;
                float2 pf = __half22float2(*(__half2*)&pe);
                sum += pf.x + pf.y;
            }
            sum += __shfl_xor_sync(0xffffffffu, sum, 1);
            sum += __shfl_xor_sync(0xffffffffu, sum, 2);
            l_[r] = l_[r] * esc + sum;
            m_[r] = mx;
#pragma unroll
            for (int nb = 0; nb < 8; nb++) {
                o[nb][2 * r]     *= esc;
                o[nb][2 * r + 1] *= esc;
            }
        }

        if (do_qk) {
#pragma unroll
            for (int nb = 0; nb < 8; nb++)
#pragma unroll
                for (int j = 0; j < 4; j++) s[nb][j] = 0.f;
        }

        // interleaved: S_{t+1} = Q K_{t+1}  +  O += P_t V_t (register P)
#pragma unroll
        for (int u = 0; u < 4; u++) {
            if (do_qk) {
                uint32_t bh[16];
#pragma unroll
                for (int bp = 0; bp < 4; bp++) {
                    uint32_t roff = (bp * 16 + b_nboff + b_row) * KS_ROWB
                                  + u * 32 + b_half * 16;
                    ldsm_x4(&bh[bp * 4], ksN + roff);
                }
#pragma unroll
                for (int nb = 0; nb < 8; nb++)
                    mma_f16(s[nb], qh[u], &bh[nb * 2]);
            }
            {
                uint32_t pa[4] = {pk[0][2 * u], pk[1][2 * u],
                                  pk[0][2 * u + 1], pk[1][2 * u + 1]};
#pragma unroll
                for (int np = 0; np < 4; np++) {
                    uint32_t t4[4];
                    ldsm_x4t(t4, vS + (u * 16 + v_row) * KS_ROWB
                                 + (2 * np + v_hi) * 16);
                    mma_f16(o[2 * np],     pa, t4);
                    mma_f16(o[2 * np + 1], pa, t4 + 2);
                }
            }
        }
    }

    // epilogue: normalize, write fp16 context [s][dmodel]
#pragma unroll
    for (int r = 0; r < 2; r++) {
        float inv = 1.f / l_[r];
        int qrow = q0 + w * 16 + g + r * 8;
        __half* dst = g_Ctx + (size_t)qrow * DMODEL + head * DHEAD + 2 * tg;
#pragma unroll
        for (int nb = 0; nb < 8; nb++) {
            *(uint32_t*)(dst + nb * 8) =
                packh2(o[nb][2 * r] * inv, o[nb][2 * r + 1] * inv);
        }
    }
}

// ---------------------------------------------------------------------------
extern "C" void kernel_launch(void* const* d_in, const int* in_sizes, int n_in,
                              void* d_out, int out_size)
{
    const float* q  = (const float*)d_in[0];
    const float* k  = (const float*)d_in[1];
    const float* v  = (const float*)d_in[2];
    const float* wq = (const float*)d_in[3];
    const float* bq = (const float*)d_in[4];
    const float* wk = (const float*)d_in[5];
    const float* bk = (const float*)d_in[6];
    const float* wv = (const float*)d_in[7];
    const float* bv = (const float*)d_in[8];
    const float* wo = (const float*)d_in[9];
    const float* bo = (const float*)d_in[10];
    float* out = (float*)d_out;

    cudaFuncSetAttribute(gemm_qkv, cudaFuncAttributeMaxDynamicSharedMemorySize, GEMM_SMEM_BYTES);
    cudaFuncSetAttribute(gemm_out, cudaFuncAttributeMaxDynamicSharedMemorySize, GEMM_SMEM_BYTES);
    cudaFuncSetAttribute(flash_attn_mma, cudaFuncAttributeMaxDynamicSharedMemorySize, ATTN_SMEM_BYTES);

    round_pre<<<(PRE_TOTAL + 255) / 256, 256>>>(q, k, v, wq, wk, wv, wo);

    gemm_qkv<<<dim3(DMODEL / 128, S_LEN / 64, 3), 256, GEMM_SMEM_BYTES>>>(bq, bk, bv);

    flash_attn_mma<<<dim3(S_LEN / 64, NHEADS), 128, ATTN_SMEM_BYTES>>>();

    gemm_out<<<dim3(DMODEL / 128, S_LEN / 64), 256, GEMM_SMEM_BYTES>>>(bo, out);
}